// round 2
// baseline (speedup 1.0000x reference)
#include <cuda_runtime.h>
#include <cuda_bf16.h>
#include <math.h>

// Problem constants
#define HID 2048
#define NH  16
#define LAT 512
#define RR  32
#define DH  128
#define CC  96
#define BB  2
#define SS  2048
#define MM  (BB*SS)   // 4096

// -------- scratch (device globals; no runtime allocation) --------
__device__ float g_qlat [MM*LAT];
__device__ float g_kvlat[MM*LAT];
__device__ float g_qc   [MM*(CC*NH)];
__device__ float g_qr   [MM*(RR*NH)];
__device__ float g_kc   [MM*(CC*NH)];
__device__ float g_kr   [MM*RR];
__device__ float g_v    [MM*HID];
__device__ float g_q    [MM*HID];
__device__ float g_k    [MM*HID];
__device__ float g_ctx  [MM*HID];

// ==================== SGEMM: C[M,N] = A[M,K] @ W[N,K]^T (+bias) ====================
// 128x128 tile, BK=8, 256 threads, 8x8 per-thread microtile.
__global__ __launch_bounds__(256) void sgemm_kernel(
    const float* __restrict__ A, const float* __restrict__ W,
    const float* __restrict__ bias, float* __restrict__ C,
    int M, int N, int K)
{
    __shared__ float As[8][128];
    __shared__ float Bs[8][128];

    const int bm = blockIdx.y * 128;
    const int bn = blockIdx.x * 128;
    const int tid = threadIdx.x;
    const int lr = tid >> 1;            // 0..127 tile row
    const int lc = (tid & 1) << 2;      // 0 or 4
    const int tx = tid & 15;            // 0..15
    const int ty = tid >> 4;            // 0..15

    float acc[8][8];
#pragma unroll
    for (int i = 0; i < 8; i++)
#pragma unroll
        for (int j = 0; j < 8; j++) acc[i][j] = 0.f;

    const float* Aptr = A + (long)(bm + lr) * K + lc;
    const bool wvalid = (bn + lr) < N;
    const float* Wptr = W + (long)(wvalid ? (bn + lr) : 0) * K + lc;

    for (int k0 = 0; k0 < K; k0 += 8) {
        float4 a4 = *(const float4*)(Aptr + k0);
        float4 b4 = make_float4(0.f, 0.f, 0.f, 0.f);
        if (wvalid) b4 = *(const float4*)(Wptr + k0);

        __syncthreads();
        As[lc+0][lr] = a4.x; As[lc+1][lr] = a4.y; As[lc+2][lr] = a4.z; As[lc+3][lr] = a4.w;
        Bs[lc+0][lr] = b4.x; Bs[lc+1][lr] = b4.y; Bs[lc+2][lr] = b4.z; Bs[lc+3][lr] = b4.w;
        __syncthreads();

#pragma unroll
        for (int kk = 0; kk < 8; kk++) {
            float a[8], b[8];
            *(float4*)&a[0] = *(const float4*)&As[kk][ty*8];
            *(float4*)&a[4] = *(const float4*)&As[kk][ty*8+4];
            *(float4*)&b[0] = *(const float4*)&Bs[kk][tx*8];
            *(float4*)&b[4] = *(const float4*)&Bs[kk][tx*8+4];
#pragma unroll
            for (int i = 0; i < 8; i++)
#pragma unroll
                for (int j = 0; j < 8; j++)
                    acc[i][j] = fmaf(a[i], b[j], acc[i][j]);
        }
    }

#pragma unroll
    for (int i = 0; i < 8; i++) {
        int row = bm + ty*8 + i;
#pragma unroll
        for (int j = 0; j < 8; j++) {
            int col = bn + tx*8 + j;
            if (col < N) {
                float r = acc[i][j];
                if (bias) r += bias[col];
                C[(long)row * N + col] = r;
            }
        }
    }
}

// ==================== RoPE assembly ====================
// q[t, h, d]: d<96 -> q_c[t, h*96+d]; d>=96 -> rope(q_r[t, h*32 + (d-96)])
__global__ void assemble_q_kernel(const float* __restrict__ qc,
                                  const float* __restrict__ qr,
                                  float* __restrict__ q)
{
    int idx = blockIdx.x * blockDim.x + threadIdx.x;
    if (idx >= MM*HID) return;
    int d = idx & 127;
    int h = (idx >> 7) & 15;
    int t = idx >> 11;         // 0..4095
    int s = t & (SS - 1);      // position in sequence
    float val;
    if (d < CC) {
        val = qc[(long)t * (CC*NH) + h*CC + d];
    } else {
        int r = d - CC;
        int i = r & 15;
        float inv = powf(10000.0f, -(float)i / 16.0f);
        float freq = (float)s * inv;
        float cs, sn;
        sincosf(freq, &sn, &cs);
        const float* base = qr + (long)t * (RR*NH) + h*RR;
        float x = base[r];
        float xr = (r < 16) ? -base[r + 16] : base[r - 16];
        val = x * cs + xr * sn;
    }
    q[idx] = val;
}

__global__ void assemble_k_kernel(const float* __restrict__ kc,
                                  const float* __restrict__ kr,
                                  float* __restrict__ k)
{
    int idx = blockIdx.x * blockDim.x + threadIdx.x;
    if (idx >= MM*HID) return;
    int d = idx & 127;
    int h = (idx >> 7) & 15;
    int t = idx >> 11;
    int s = t & (SS - 1);
    float val;
    if (d < CC) {
        val = kc[(long)t * (CC*NH) + h*CC + d];
    } else {
        int r = d - CC;
        int i = r & 15;
        float inv = powf(10000.0f, -(float)i / 16.0f);
        float freq = (float)s * inv;
        float cs, sn;
        sincosf(freq, &sn, &cs);
        const float* base = kr + (long)t * RR;   // shared across heads
        float x = base[r];
        float xr = (r < 16) ? -base[r + 16] : base[r - 16];
        val = x * cs + xr * sn;
    }
    k[idx] = val;
}

// ==================== Flash attention (causal, fp32) ====================
// Tiles: 64 q-rows x 64 k-rows, D=128. 128 threads: tx=tid&7 (k-cols j*8+tx),
// ty=tid>>3 (4 q-rows each). Padded smem strides kill bank conflicts.
#define KST 132   // K/V smem row stride (floats)
#define PST 65    // P smem row stride

__global__ __launch_bounds__(128) void flash_kernel(
    const float* __restrict__ Q, const float* __restrict__ Kt,
    const float* __restrict__ Vt, float* __restrict__ O)
{
    extern __shared__ float sm[];
    float* Qs = sm;                    // 64*128
    float* Ks = Qs + 64*128;           // 64*KST
    float* Vs = Ks + 64*KST;           // 64*KST
    float* Ps = Vs + 64*KST;           // 64*PST

    const int qb = blockIdx.x;
    const int h  = blockIdx.y;
    const int b  = blockIdx.z;
    const int tid = threadIdx.x;
    const int tx = tid & 7;
    const int ty = tid >> 3;
    const int RS = NH * DH;            // 2048 row stride in tokens
    const long base = ((long)b * SS * NH + h) * DH;

    // load Q tile (64 x 128)
    {
        const float* src = Q + base + (long)(qb * 64) * RS;
#pragma unroll
        for (int i = 0; i < 16; i++) {
            int idx = tid + i * 128;
            int r = idx >> 5, c = (idx & 31) << 2;
            *(float4*)(Qs + r * 128 + c) = *(const float4*)(src + (long)r * RS + c);
        }
    }

    float m[4], l[4], acc[4][16];
#pragma unroll
    for (int rr = 0; rr < 4; rr++) {
        m[rr] = -1e30f; l[rr] = 0.f;
#pragma unroll
        for (int cc = 0; cc < 16; cc++) acc[rr][cc] = 0.f;
    }
    const float scale = 0.08838834764831845f;  // 1/sqrt(128)

    for (int kb = 0; kb <= qb; kb++) {
        const float* ksrc = Kt + base + (long)(kb * 64) * RS;
        const float* vsrc = Vt + base + (long)(kb * 64) * RS;
        __syncthreads();
#pragma unroll
        for (int i = 0; i < 16; i++) {
            int idx = tid + i * 128;
            int r = idx >> 5, c = (idx & 31) << 2;
            *(float4*)(Ks + r * KST + c) = *(const float4*)(ksrc + (long)r * RS + c);
            *(float4*)(Vs + r * KST + c) = *(const float4*)(vsrc + (long)r * RS + c);
        }
        __syncthreads();

        // S = Q K^T  (thread owns rows ty*4+rr, cols j*8+tx)
        float s[4][8];
#pragma unroll
        for (int rr = 0; rr < 4; rr++)
#pragma unroll
            for (int j = 0; j < 8; j++) s[rr][j] = 0.f;

        for (int d = 0; d < 128; d += 4) {
            float4 qv[4];
#pragma unroll
            for (int rr = 0; rr < 4; rr++)
                qv[rr] = *(const float4*)(Qs + (ty*4+rr)*128 + d);
#pragma unroll
            for (int j = 0; j < 8; j++) {
                float4 kv = *(const float4*)(Ks + (j*8+tx)*KST + d);
#pragma unroll
                for (int rr = 0; rr < 4; rr++) {
                    s[rr][j] = fmaf(qv[rr].x, kv.x, s[rr][j]);
                    s[rr][j] = fmaf(qv[rr].y, kv.y, s[rr][j]);
                    s[rr][j] = fmaf(qv[rr].z, kv.z, s[rr][j]);
                    s[rr][j] = fmaf(qv[rr].w, kv.w, s[rr][j]);
                }
            }
        }
#pragma unroll
        for (int rr = 0; rr < 4; rr++)
#pragma unroll
            for (int j = 0; j < 8; j++) s[rr][j] *= scale;

        if (kb == qb) {
#pragma unroll
            for (int rr = 0; rr < 4; rr++) {
                int qrow = qb*64 + ty*4 + rr;
#pragma unroll
                for (int j = 0; j < 8; j++) {
                    int kcol = kb*64 + j*8 + tx;
                    if (kcol > qrow) s[rr][j] = -10000.0f;
                }
            }
        }

        // online softmax update
#pragma unroll
        for (int rr = 0; rr < 4; rr++) {
            float mx = s[rr][0];
#pragma unroll
            for (int j = 1; j < 8; j++) mx = fmaxf(mx, s[rr][j]);
            mx = fmaxf(mx, __shfl_xor_sync(0xffffffffu, mx, 1));
            mx = fmaxf(mx, __shfl_xor_sync(0xffffffffu, mx, 2));
            mx = fmaxf(mx, __shfl_xor_sync(0xffffffffu, mx, 4));
            float mnew = fmaxf(m[rr], mx);
            float alpha = __expf(m[rr] - mnew);
            float sum = 0.f;
#pragma unroll
            for (int j = 0; j < 8; j++) {
                float p = __expf(s[rr][j] - mnew);
                s[rr][j] = p;
                sum += p;
            }
            sum += __shfl_xor_sync(0xffffffffu, sum, 1);
            sum += __shfl_xor_sync(0xffffffffu, sum, 2);
            sum += __shfl_xor_sync(0xffffffffu, sum, 4);
            l[rr] = l[rr] * alpha + sum;
            m[rr] = mnew;
#pragma unroll
            for (int cc = 0; cc < 16; cc++) acc[rr][cc] *= alpha;
        }

        // stage P
#pragma unroll
        for (int rr = 0; rr < 4; rr++)
#pragma unroll
            for (int j = 0; j < 8; j++)
                Ps[(ty*4+rr)*PST + j*8 + tx] = s[rr][j];
        __syncthreads();

        // O += P @ V  (thread owns O cols cc*8+tx)
        for (int k = 0; k < 64; k++) {
            float p[4];
#pragma unroll
            for (int rr = 0; rr < 4; rr++) p[rr] = Ps[(ty*4+rr)*PST + k];
#pragma unroll
            for (int cc = 0; cc < 16; cc++) {
                float vv = Vs[k*KST + cc*8 + tx];
#pragma unroll
                for (int rr = 0; rr < 4; rr++)
                    acc[rr][cc] = fmaf(p[rr], vv, acc[rr][cc]);
            }
        }
    }

    // write out
#pragma unroll
    for (int rr = 0; rr < 4; rr++) {
        int row = qb*64 + ty*4 + rr;
        float inv = 1.0f / l[rr];
#pragma unroll
        for (int cc = 0; cc < 16; cc++)
            O[base + (long)row * RS + cc*8 + tx] = acc[rr][cc] * inv;
    }
}

// ==================== launcher ====================
static inline void launch_gemm(const float* A, const float* W, const float* bias,
                               float* C, int M, int N, int K, cudaStream_t st = 0)
{
    dim3 grid((N + 127) / 128, (M + 127) / 128);
    sgemm_kernel<<<grid, 256, 0, st>>>(A, W, bias, C, M, N, K);
}

extern "C" void kernel_launch(void* const* d_in, const int* in_sizes, int n_in,
                              void* d_out, int out_size)
{
    const float* x       = (const float*)d_in[0];
    const float* Wq_down = (const float*)d_in[1];
    const float* Wq_up   = (const float*)d_in[2];
    const float* Wq_rope = (const float*)d_in[3];
    const float* Wkv_down= (const float*)d_in[4];
    const float* Wk_up   = (const float*)d_in[5];
    const float* Wk_rope = (const float*)d_in[6];
    const float* Wv_up   = (const float*)d_in[7];
    const float* Wo      = (const float*)d_in[8];
    const float* bo      = (const float*)d_in[9];
    float* out = (float*)d_out;

    float *qlat, *kvlat, *qc, *qr, *kc, *kr, *v, *q, *k, *ctx;
    cudaGetSymbolAddress((void**)&qlat,  g_qlat);
    cudaGetSymbolAddress((void**)&kvlat, g_kvlat);
    cudaGetSymbolAddress((void**)&qc,    g_qc);
    cudaGetSymbolAddress((void**)&qr,    g_qr);
    cudaGetSymbolAddress((void**)&kc,    g_kc);
    cudaGetSymbolAddress((void**)&kr,    g_kr);
    cudaGetSymbolAddress((void**)&v,     g_v);
    cudaGetSymbolAddress((void**)&q,     g_q);
    cudaGetSymbolAddress((void**)&k,     g_k);
    cudaGetSymbolAddress((void**)&ctx,   g_ctx);

    // projections
    launch_gemm(x,     Wq_down,  nullptr, qlat,  MM, LAT,   HID);
    launch_gemm(x,     Wkv_down, nullptr, kvlat, MM, LAT,   HID);
    launch_gemm(x,     Wk_rope,  nullptr, kr,    MM, RR,    HID);
    launch_gemm(qlat,  Wq_up,    nullptr, qc,    MM, CC*NH, LAT);
    launch_gemm(qlat,  Wq_rope,  nullptr, qr,    MM, RR*NH, LAT);
    launch_gemm(kvlat, Wk_up,    nullptr, kc,    MM, CC*NH, LAT);
    launch_gemm(kvlat, Wv_up,    nullptr, v,     MM, HID,   LAT);

    // rope + head assembly
    {
        int total = MM * HID;
        int threads = 256;
        int blocks = (total + threads - 1) / threads;
        assemble_q_kernel<<<blocks, threads>>>(qc, qr, q);
        assemble_k_kernel<<<blocks, threads>>>(kc, kr, k);
    }

    // flash attention
    {
        size_t smem = (size_t)(64*128 + 64*KST + 64*KST + 64*PST) * sizeof(float);
        cudaFuncSetAttribute(flash_kernel,
                             cudaFuncAttributeMaxDynamicSharedMemorySize, (int)smem);
        dim3 grid(SS / 64, NH, BB);
        flash_kernel<<<grid, 128, smem>>>(q, k, v, ctx);
    }

    // output projection + bias
    launch_gemm(ctx, Wo, bo, out, MM, HID, HID);
}

// round 4
// speedup vs baseline: 1.0602x; 1.0602x over previous
#include <cuda_runtime.h>
#include <cuda_bf16.h>
#include <math.h>

// Problem constants
#define HID 2048
#define NH  16
#define LAT 512
#define RR  32
#define DH  128
#define CC  96
#define BB  2
#define SS  2048
#define MM  (BB*SS)   // 4096

typedef unsigned long long ull;

// ---------------- f32x2 packed helpers (Blackwell FFMA2 path) ----------------
__device__ __forceinline__ ull pack2(float x, float y) {
    ull r;
    asm("mov.b64 %0, {%1, %2};" : "=l"(r) : "r"(__float_as_uint(x)), "r"(__float_as_uint(y)));
    return r;
}
__device__ __forceinline__ ull dup2(float x) {
    ull r;
    asm("mov.b64 %0, {%1, %1};" : "=l"(r) : "r"(__float_as_uint(x)));
    return r;
}
__device__ __forceinline__ float2 unpack2(ull a) {
    unsigned lo, hi;
    asm("mov.b64 {%0, %1}, %2;" : "=r"(lo), "=r"(hi) : "l"(a));
    return make_float2(__uint_as_float(lo), __uint_as_float(hi));
}
__device__ __forceinline__ void fma2(ull& d, ull a, ull b) {
    asm("fma.rn.f32x2 %0, %1, %2, %0;" : "+l"(d) : "l"(a), "l"(b));
}
__device__ __forceinline__ void mul2(ull& d, ull a) {
    asm("mul.rn.f32x2 %0, %0, %1;" : "+l"(d) : "l"(a));
}
__device__ __forceinline__ void add2(ull& d, ull a) {
    asm("add.rn.f32x2 %0, %0, %1;" : "+l"(d) : "l"(a));
}

// -------- scratch (device globals; no runtime allocation) --------
__device__ float g_qlat [MM*LAT];
__device__ float g_kvlat[MM*LAT];
__device__ float g_qc   [MM*(CC*NH)];
__device__ float g_qr   [MM*(RR*NH)];
__device__ float g_kc   [MM*(CC*NH)];
__device__ float g_kr   [MM*RR];
__device__ float g_v    [MM*HID];
__device__ float g_q    [MM*HID];
__device__ float g_k    [MM*HID];
__device__ float g_ctx  [MM*HID];
__device__ float g_rope [SS*16*2];   // [s][i] -> cos, sin

// ==================== SGEMM: C[M,N] = A[M,K] @ W[N,K]^T (+bias) ====================
// 128x128 tile, BK=8, 256 threads, 8x8 per-thread microtile, f32x2 math,
// register-prefetched global loads.
__global__ __launch_bounds__(256) void sgemm_kernel(
    const float* __restrict__ A, const float* __restrict__ W,
    const float* __restrict__ bias, float* __restrict__ C,
    int M, int N, int K)
{
    __shared__ float As[8][128];
    __shared__ float Bs[8][128];

    const int bm = blockIdx.y * 128;
    const int bn = blockIdx.x * 128;
    const int tid = threadIdx.x;
    const int lr = tid >> 1;            // 0..127 tile row
    const int lc = (tid & 1) << 2;      // 0 or 4
    const int tx = tid & 15;            // 0..15
    const int ty = tid >> 4;            // 0..15

    ull acc[8][4];
#pragma unroll
    for (int i = 0; i < 8; i++)
#pragma unroll
        for (int j = 0; j < 4; j++) acc[i][j] = 0ull;

    const float* Aptr = A + (long)(bm + lr) * K + lc;
    const bool wvalid = (bn + lr) < N;
    const float* Wptr = W + (long)(wvalid ? (bn + lr) : 0) * K + lc;

    float4 a4 = *(const float4*)(Aptr);
    float4 b4 = wvalid ? *(const float4*)(Wptr) : make_float4(0.f, 0.f, 0.f, 0.f);

    for (int k0 = 0; k0 < K; k0 += 8) {
        __syncthreads();
        As[lc+0][lr] = a4.x; As[lc+1][lr] = a4.y; As[lc+2][lr] = a4.z; As[lc+3][lr] = a4.w;
        Bs[lc+0][lr] = b4.x; Bs[lc+1][lr] = b4.y; Bs[lc+2][lr] = b4.z; Bs[lc+3][lr] = b4.w;
        __syncthreads();

        if (k0 + 8 < K) {
            a4 = *(const float4*)(Aptr + k0 + 8);
            if (wvalid) b4 = *(const float4*)(Wptr + k0 + 8);
        }

#pragma unroll
        for (int kk = 0; kk < 8; kk++) {
            float4 af0 = *(const float4*)&As[kk][ty*8];
            float4 af1 = *(const float4*)&As[kk][ty*8+4];
            ulonglong2 bq0 = *(const ulonglong2*)&Bs[kk][tx*8];
            ulonglong2 bq1 = *(const ulonglong2*)&Bs[kk][tx*8+4];
            ull b2[4] = {bq0.x, bq0.y, bq1.x, bq1.y};
            ull ad[8];
            ad[0] = dup2(af0.x); ad[1] = dup2(af0.y);
            ad[2] = dup2(af0.z); ad[3] = dup2(af0.w);
            ad[4] = dup2(af1.x); ad[5] = dup2(af1.y);
            ad[6] = dup2(af1.z); ad[7] = dup2(af1.w);
#pragma unroll
            for (int i = 0; i < 8; i++)
#pragma unroll
                for (int j = 0; j < 4; j++)
                    fma2(acc[i][j], ad[i], b2[j]);
        }
    }

#pragma unroll
    for (int i = 0; i < 8; i++) {
        int row = bm + ty*8 + i;
#pragma unroll
        for (int j = 0; j < 4; j++) {
            int col = bn + tx*8 + j*2;
            if (col < N) {
                ull r = acc[i][j];
                if (bias) add2(r, pack2(bias[col], bias[col+1]));
                *(ull*)(&C[(long)row * N + col]) = r;
            }
        }
    }
}

// ==================== RoPE table ====================
__global__ void rope_table_kernel(float* __restrict__ tab)
{
    int idx = blockIdx.x * blockDim.x + threadIdx.x;   // s*16 + i
    if (idx >= SS * 16) return;
    int i = idx & 15;
    int s = idx >> 4;
    float inv = powf(10000.0f, -(float)i / 16.0f);
    float freq = (float)s * inv;
    float cs, sn;
    sincosf(freq, &sn, &cs);
    tab[idx*2+0] = cs;
    tab[idx*2+1] = sn;
}

// ==================== head assembly + RoPE ====================
__global__ void assemble_q_kernel(const float* __restrict__ qc,
                                  const float* __restrict__ qr,
                                  const float* __restrict__ tab,
                                  float* __restrict__ q)
{
    int idx = blockIdx.x * blockDim.x + threadIdx.x;
    if (idx >= MM*HID) return;
    int d = idx & 127;
    int h = (idx >> 7) & 15;
    int t = idx >> 11;
    int s = t & (SS - 1);
    float val;
    if (d < CC) {
        val = qc[(long)t * (CC*NH) + h*CC + d];
    } else {
        int r = d - CC;
        int i = r & 15;
        float cs = tab[(s*16+i)*2+0];
        float sn = tab[(s*16+i)*2+1];
        const float* base = qr + (long)t * (RR*NH) + h*RR;
        float x = base[r];
        float xr = (r < 16) ? -base[r + 16] : base[r - 16];
        val = x * cs + xr * sn;
    }
    q[idx] = val;
}

__global__ void assemble_k_kernel(const float* __restrict__ kc,
                                  const float* __restrict__ kr,
                                  const float* __restrict__ tab,
                                  float* __restrict__ k)
{
    int idx = blockIdx.x * blockDim.x + threadIdx.x;
    if (idx >= MM*HID) return;
    int d = idx & 127;
    int h = (idx >> 7) & 15;
    int t = idx >> 11;
    int s = t & (SS - 1);
    float val;
    if (d < CC) {
        val = kc[(long)t * (CC*NH) + h*CC + d];
    } else {
        int r = d - CC;
        int i = r & 15;
        float cs = tab[(s*16+i)*2+0];
        float sn = tab[(s*16+i)*2+1];
        const float* base = kr + (long)t * RR;   // shared across heads
        float x = base[r];
        float xr = (r < 16) ? -base[r + 16] : base[r - 16];
        val = x * cs + xr * sn;
    }
    k[idx] = val;
}

// ==================== Flash attention (causal, f32x2) ====================
// 64 q-rows x 64 k-rows per tile, D=128, 256 threads (8 warps).
// tx=tid&7 owns k-col group j*8+tx and O col pairs tx*2+p*16; ty=tid>>3 owns
// q rows ty*2+{0,1}. Padded smem strides keep all LDS phases conflict-free.
#define KST 132   // K/V smem row stride (floats)
#define PST 65    // P smem row stride

__global__ __launch_bounds__(256) void flash_kernel(
    const float* __restrict__ Q, const float* __restrict__ Kt,
    const float* __restrict__ Vt, float* __restrict__ O)
{
    extern __shared__ float sm[];
    float* Qs = sm;                    // 64*128
    float* Ks = Qs + 64*128;           // 64*KST
    float* Vs = Ks + 64*KST;           // 64*KST
    float* Ps = Vs + 64*KST;           // 64*PST

    const int qb = blockIdx.x;
    const int h  = blockIdx.y;
    const int b  = blockIdx.z;
    const int tid = threadIdx.x;
    const int tx = tid & 7;
    const int ty = tid >> 3;           // 0..31
    const int RS = NH * DH;            // 2048
    const long base = ((long)b * SS * NH + h) * DH;

    // load Q tile (64 x 128): 8192 floats / 256 threads = 8 float4 each
    {
        const float* src = Q + base + (long)(qb * 64) * RS;
#pragma unroll
        for (int i = 0; i < 8; i++) {
            int idx = tid + i * 256;
            int r = idx >> 5, c = (idx & 31) << 2;
            *(float4*)(Qs + r * 128 + c) = *(const float4*)(src + (long)r * RS + c);
        }
    }

    float m[2], l[2];
    ull acc[2][8];
#pragma unroll
    for (int rr = 0; rr < 2; rr++) {
        m[rr] = -1e30f; l[rr] = 0.f;
#pragma unroll
        for (int p = 0; p < 8; p++) acc[rr][p] = 0ull;
    }
    const float scale = 0.08838834764831845f;  // 1/sqrt(128)

    for (int kb = 0; kb <= qb; kb++) {
        const float* ksrc = Kt + base + (long)(kb * 64) * RS;
        const float* vsrc = Vt + base + (long)(kb * 64) * RS;
        __syncthreads();
#pragma unroll
        for (int i = 0; i < 8; i++) {
            int idx = tid + i * 256;
            int r = idx >> 5, c = (idx & 31) << 2;
            *(float4*)(Ks + r * KST + c) = *(const float4*)(ksrc + (long)r * RS + c);
            *(float4*)(Vs + r * KST + c) = *(const float4*)(vsrc + (long)r * RS + c);
        }
        __syncthreads();

        // ---- S = Q K^T via f32x2 pairs along d ----
        ull s2[2][8];
#pragma unroll
        for (int rr = 0; rr < 2; rr++)
#pragma unroll
            for (int j = 0; j < 8; j++) s2[rr][j] = 0ull;

        for (int d = 0; d < 128; d += 4) {
            ulonglong2 q0 = *(const ulonglong2*)(Qs + (ty*2+0)*128 + d);
            ulonglong2 q1 = *(const ulonglong2*)(Qs + (ty*2+1)*128 + d);
#pragma unroll
            for (int j = 0; j < 8; j++) {
                ulonglong2 kq = *(const ulonglong2*)(Ks + (j*8+tx)*KST + d);
                fma2(s2[0][j], q0.x, kq.x);
                fma2(s2[0][j], q0.y, kq.y);
                fma2(s2[1][j], q1.x, kq.x);
                fma2(s2[1][j], q1.y, kq.y);
            }
        }

        float s[2][8];
#pragma unroll
        for (int rr = 0; rr < 2; rr++)
#pragma unroll
            for (int j = 0; j < 8; j++) {
                float2 t2 = unpack2(s2[rr][j]);
                s[rr][j] = (t2.x + t2.y) * scale;
            }

        if (kb == qb) {
#pragma unroll
            for (int rr = 0; rr < 2; rr++) {
                int qrow = qb*64 + ty*2 + rr;
#pragma unroll
                for (int j = 0; j < 8; j++) {
                    int kcol = kb*64 + j*8 + tx;
                    if (kcol > qrow) s[rr][j] = -10000.0f;
                }
            }
        }

        // ---- online softmax ----
#pragma unroll
        for (int rr = 0; rr < 2; rr++) {
            float mx = s[rr][0];
#pragma unroll
            for (int j = 1; j < 8; j++) mx = fmaxf(mx, s[rr][j]);
            mx = fmaxf(mx, __shfl_xor_sync(0xffffffffu, mx, 1));
            mx = fmaxf(mx, __shfl_xor_sync(0xffffffffu, mx, 2));
            mx = fmaxf(mx, __shfl_xor_sync(0xffffffffu, mx, 4));
            float mnew = fmaxf(m[rr], mx);
            float alpha = __expf(m[rr] - mnew);
            float sum = 0.f;
#pragma unroll
            for (int j = 0; j < 8; j++) {
                float p = __expf(s[rr][j] - mnew);
                s[rr][j] = p;
                sum += p;
            }
            sum += __shfl_xor_sync(0xffffffffu, sum, 1);
            sum += __shfl_xor_sync(0xffffffffu, sum, 2);
            sum += __shfl_xor_sync(0xffffffffu, sum, 4);
            l[rr] = l[rr] * alpha + sum;
            m[rr] = mnew;
            ull al = dup2(alpha);
#pragma unroll
            for (int p = 0; p < 8; p++) mul2(acc[rr][p], al);
        }

        // ---- stage P ----
#pragma unroll
        for (int rr = 0; rr < 2; rr++)
#pragma unroll
            for (int j = 0; j < 8; j++)
                Ps[(ty*2+rr)*PST + j*8 + tx] = s[rr][j];
        __syncthreads();

        // ---- O += P @ V (f32x2 over column pairs) ----
        for (int k = 0; k < 64; k++) {
            ull p0 = dup2(Ps[(ty*2+0)*PST + k]);
            ull p1 = dup2(Ps[(ty*2+1)*PST + k]);
#pragma unroll
            for (int p = 0; p < 8; p++) {
                ull v2 = *(const ull*)(Vs + k*KST + tx*2 + p*16);
                fma2(acc[0][p], p0, v2);
                fma2(acc[1][p], p1, v2);
            }
        }
    }

    // write out
#pragma unroll
    for (int rr = 0; rr < 2; rr++) {
        int row = qb*64 + ty*2 + rr;
        ull iv = dup2(1.0f / l[rr]);
#pragma unroll
        for (int p = 0; p < 8; p++) {
            mul2(acc[rr][p], iv);
            *(ull*)(&O[base + (long)row * RS + tx*2 + p*16]) = acc[rr][p];
        }
    }
}

// ==================== launcher ====================
static inline void launch_gemm(const float* A, const float* W, const float* bias,
                               float* C, int M, int N, int K)
{
    dim3 grid((N + 127) / 128, (M + 127) / 128);
    sgemm_kernel<<<grid, 256>>>(A, W, bias, C, M, N, K);
}

extern "C" void kernel_launch(void* const* d_in, const int* in_sizes, int n_in,
                              void* d_out, int out_size)
{
    const float* x       = (const float*)d_in[0];
    const float* Wq_down = (const float*)d_in[1];
    const float* Wq_up   = (const float*)d_in[2];
    const float* Wq_rope = (const float*)d_in[3];
    const float* Wkv_down= (const float*)d_in[4];
    const float* Wk_up   = (const float*)d_in[5];
    const float* Wk_rope = (const float*)d_in[6];
    const float* Wv_up   = (const float*)d_in[7];
    const float* Wo      = (const float*)d_in[8];
    const float* bo      = (const float*)d_in[9];
    float* out = (float*)d_out;

    float *qlat, *kvlat, *qc, *qr, *kc, *kr, *v, *q, *k, *ctx, *tab;
    cudaGetSymbolAddress((void**)&qlat,  g_qlat);
    cudaGetSymbolAddress((void**)&kvlat, g_kvlat);
    cudaGetSymbolAddress((void**)&qc,    g_qc);
    cudaGetSymbolAddress((void**)&qr,    g_qr);
    cudaGetSymbolAddress((void**)&kc,    g_kc);
    cudaGetSymbolAddress((void**)&kr,    g_kr);
    cudaGetSymbolAddress((void**)&v,     g_v);
    cudaGetSymbolAddress((void**)&q,     g_q);
    cudaGetSymbolAddress((void**)&k,     g_k);
    cudaGetSymbolAddress((void**)&ctx,   g_ctx);
    cudaGetSymbolAddress((void**)&tab,   g_rope);

    // rope table (cheap; recomputed every call — deterministic)
    rope_table_kernel<<<(SS*16 + 255)/256, 256>>>(tab);

    // projections
    launch_gemm(x,     Wq_down,  nullptr, qlat,  MM, LAT,   HID);
    launch_gemm(x,     Wkv_down, nullptr, kvlat, MM, LAT,   HID);
    launch_gemm(x,     Wk_rope,  nullptr, kr,    MM, RR,    HID);
    launch_gemm(qlat,  Wq_up,    nullptr, qc,    MM, CC*NH, LAT);
    launch_gemm(qlat,  Wq_rope,  nullptr, qr,    MM, RR*NH, LAT);
    launch_gemm(kvlat, Wk_up,    nullptr, kc,    MM, CC*NH, LAT);
    launch_gemm(kvlat, Wv_up,    nullptr, v,     MM, HID,   LAT);

    // rope + head assembly
    {
        int total = MM * HID;
        int threads = 256;
        int blocks = (total + threads - 1) / threads;
        assemble_q_kernel<<<blocks, threads>>>(qc, qr, tab, q);
        assemble_k_kernel<<<blocks, threads>>>(kc, kr, tab, k);
    }

    // flash attention
    {
        size_t smem = (size_t)(64*128 + 64*KST + 64*KST + 64*PST) * sizeof(float);
        cudaFuncSetAttribute(flash_kernel,
                             cudaFuncAttributeMaxDynamicSharedMemorySize, (int)smem);
        dim3 grid(SS / 64, NH, BB);
        flash_kernel<<<grid, 256, smem>>>(q, k, v, ctx);
    }

    // output projection + bias
    launch_gemm(ctx, Wo, bo, out, MM, HID, HID);
}

// round 6
// speedup vs baseline: 1.5715x; 1.4823x over previous
#include <cuda_runtime.h>
#include <cuda_bf16.h>
#include <math.h>
#include <stdint.h>

// Problem constants
#define HID 2048
#define NH  16
#define LAT 512
#define RR  32
#define DH  128
#define CC  96
#define BB  2
#define SS  2048
#define MM  (BB*SS)   // 4096

typedef unsigned long long ull;

// ---------------- f32x2 packed helpers (flash kernel) ----------------
__device__ __forceinline__ ull dup2(float x) {
    ull r;
    asm("mov.b64 %0, {%1, %1};" : "=l"(r) : "r"(__float_as_uint(x)));
    return r;
}
__device__ __forceinline__ float2 unpack2(ull a) {
    unsigned lo, hi;
    asm("mov.b64 {%0, %1}, %2;" : "=r"(lo), "=r"(hi) : "l"(a));
    return make_float2(__uint_as_float(lo), __uint_as_float(hi));
}
__device__ __forceinline__ void fma2(ull& d, ull a, ull b) {
    asm("fma.rn.f32x2 %0, %1, %2, %0;" : "+l"(d) : "l"(a), "l"(b));
}
__device__ __forceinline__ void mul2(ull& d, ull a) {
    asm("mul.rn.f32x2 %0, %0, %1;" : "+l"(d) : "l"(a));
}

// ---------------- bf16 mma.sync helpers ----------------
__device__ __forceinline__ void mma16816(float* c, const uint32_t* a, const uint32_t* b) {
    asm volatile(
        "mma.sync.aligned.m16n8k16.row.col.f32.bf16.bf16.f32 "
        "{%0,%1,%2,%3}, {%4,%5,%6,%7}, {%8,%9}, {%0,%1,%2,%3};"
        : "+f"(c[0]), "+f"(c[1]), "+f"(c[2]), "+f"(c[3])
        : "r"(a[0]), "r"(a[1]), "r"(a[2]), "r"(a[3]), "r"(b[0]), "r"(b[1]));
}

// split fp32 -> hi/lo bf16 pair (a ~= hi + lo)
__device__ __forceinline__ void split_bf16(float x, __nv_bfloat16& h, __nv_bfloat16& l) {
    h = __float2bfloat16_rn(x);
    l = __float2bfloat16_rn(x - __bfloat162float(h));
}

// -------- scratch (device globals; no runtime allocation) --------
__device__ float g_qlat [MM*LAT];
__device__ float g_kvlat[MM*LAT];
__device__ float g_qc   [MM*(CC*NH)];
__device__ float g_qr   [MM*(RR*NH)];
__device__ float g_kc   [MM*(CC*NH)];
__device__ float g_kr   [MM*RR];
__device__ float g_v    [MM*HID];
__device__ float g_q    [MM*HID];
__device__ float g_k    [MM*HID];
__device__ float g_ctx  [MM*HID];
__device__ float g_rope [SS*16*2];

// ==================== mma.sync bf16 3-pass GEMM ====================
// C[M,N] = A[M,K] @ W[N,K]^T (+bias). BM=128, BK=32.
// Each fp32 operand split into hi+lo bf16; D = AhBh + AhBl + AlBh (fp32 acc).
template<int BN, int WARPS_M, int WARPS_N>
__global__ __launch_bounds__(256) void mma_gemm_kernel(
    const float* __restrict__ A, const float* __restrict__ W,
    const float* __restrict__ bias, float* __restrict__ C,
    int M, int N, int K)
{
    constexpr int BM = 128, BK = 32, ST = 40;   // padded bf16 row stride
    constexpr int WTM = BM / WARPS_M;           // warp tile rows
    constexpr int WTN = BN / WARPS_N;           // warp tile cols
    constexpr int MT = WTM / 16;
    constexpr int NT = WTN / 8;

    __shared__ __nv_bfloat16 Ah[BM*ST], Al[BM*ST], Bh[BN*ST], Bl[BN*ST];

    const int bm = blockIdx.y * BM;
    const int bn = blockIdx.x * BN;
    const int tid = threadIdx.x;
    const int wid = tid >> 5;
    const int lane = tid & 31;
    const int wm = wid / WARPS_N;
    const int wn = wid % WARPS_N;
    const int g = lane >> 2;      // 0..7
    const int tig = lane & 3;     // 0..3

    float acc[MT][NT][4];
#pragma unroll
    for (int mt = 0; mt < MT; mt++)
#pragma unroll
        for (int nt = 0; nt < NT; nt++)
#pragma unroll
            for (int i = 0; i < 4; i++) acc[mt][nt][i] = 0.f;

    for (int k0 = 0; k0 < K; k0 += BK) {
        // ---- stage A (BM x BK) ----
#pragma unroll
        for (int it = 0; it < BM*BK/4/256; it++) {
            int f = tid + it * 256;
            int row = f >> 3, cg = f & 7;
            float4 v = *(const float4*)(A + (long)(bm + row) * K + k0 + cg * 4);
            __nv_bfloat16 hx, lx, hy, ly, hz, lz, hw, lw;
            split_bf16(v.x, hx, lx); split_bf16(v.y, hy, ly);
            split_bf16(v.z, hz, lz); split_bf16(v.w, hw, lw);
            __nv_bfloat162* ph = (__nv_bfloat162*)&Ah[row*ST + cg*4];
            __nv_bfloat162* pl = (__nv_bfloat162*)&Al[row*ST + cg*4];
            ph[0] = __nv_bfloat162(hx, hy); ph[1] = __nv_bfloat162(hz, hw);
            pl[0] = __nv_bfloat162(lx, ly); pl[1] = __nv_bfloat162(lz, lw);
        }
        // ---- stage B (BN x BK) ----
#pragma unroll
        for (int it = 0; it < BN*BK/4/256; it++) {
            int f = tid + it * 256;
            int row = f >> 3, cg = f & 7;
            float4 v = *(const float4*)(W + (long)(bn + row) * K + k0 + cg * 4);
            __nv_bfloat16 hx, lx, hy, ly, hz, lz, hw, lw;
            split_bf16(v.x, hx, lx); split_bf16(v.y, hy, ly);
            split_bf16(v.z, hz, lz); split_bf16(v.w, hw, lw);
            __nv_bfloat162* ph = (__nv_bfloat162*)&Bh[row*ST + cg*4];
            __nv_bfloat162* pl = (__nv_bfloat162*)&Bl[row*ST + cg*4];
            ph[0] = __nv_bfloat162(hx, hy); ph[1] = __nv_bfloat162(hz, hw);
            pl[0] = __nv_bfloat162(lx, ly); pl[1] = __nv_bfloat162(lz, lw);
        }
        __syncthreads();

#pragma unroll
        for (int kk = 0; kk < BK; kk += 16) {
            uint32_t afh[MT][4], afl[MT][4], bfh[NT][2], bfl[NT][2];
#pragma unroll
            for (int mt = 0; mt < MT; mt++) {
                int rb = wm * WTM + mt * 16;
                int a0 = (rb + g) * ST + kk + tig * 2;
                int a1 = (rb + g + 8) * ST + kk + tig * 2;
                afh[mt][0] = *(const uint32_t*)&Ah[a0];
                afh[mt][1] = *(const uint32_t*)&Ah[a1];
                afh[mt][2] = *(const uint32_t*)&Ah[a0 + 8];
                afh[mt][3] = *(const uint32_t*)&Ah[a1 + 8];
                afl[mt][0] = *(const uint32_t*)&Al[a0];
                afl[mt][1] = *(const uint32_t*)&Al[a1];
                afl[mt][2] = *(const uint32_t*)&Al[a0 + 8];
                afl[mt][3] = *(const uint32_t*)&Al[a1 + 8];
            }
#pragma unroll
            for (int nt = 0; nt < NT; nt++) {
                int nb = wn * WTN + nt * 8;
                int b0 = (nb + g) * ST + kk + tig * 2;
                bfh[nt][0] = *(const uint32_t*)&Bh[b0];
                bfh[nt][1] = *(const uint32_t*)&Bh[b0 + 8];
                bfl[nt][0] = *(const uint32_t*)&Bl[b0];
                bfl[nt][1] = *(const uint32_t*)&Bl[b0 + 8];
            }
#pragma unroll
            for (int mt = 0; mt < MT; mt++)
#pragma unroll
                for (int nt = 0; nt < NT; nt++) {
                    mma16816(acc[mt][nt], afh[mt], bfh[nt]);
                    mma16816(acc[mt][nt], afh[mt], bfl[nt]);
                    mma16816(acc[mt][nt], afl[mt], bfh[nt]);
                }
        }
        __syncthreads();
    }

    // ---- epilogue ----
#pragma unroll
    for (int mt = 0; mt < MT; mt++) {
        int row0 = bm + wm * WTM + mt * 16 + g;
#pragma unroll
        for (int nt = 0; nt < NT; nt++) {
            int col = bn + wn * WTN + nt * 8 + tig * 2;
            float b0 = bias ? bias[col] : 0.f;
            float b1 = bias ? bias[col + 1] : 0.f;
            float2 v0 = make_float2(acc[mt][nt][0] + b0, acc[mt][nt][1] + b1);
            float2 v1 = make_float2(acc[mt][nt][2] + b0, acc[mt][nt][3] + b1);
            *(float2*)&C[(long)row0 * N + col]       = v0;
            *(float2*)&C[(long)(row0 + 8) * N + col] = v1;
        }
    }
}

// ==================== RoPE table ====================
__global__ void rope_table_kernel(float* __restrict__ tab)
{
    int idx = blockIdx.x * blockDim.x + threadIdx.x;
    if (idx >= SS * 16) return;
    int i = idx & 15;
    int s = idx >> 4;
    float inv = powf(10000.0f, -(float)i / 16.0f);
    float freq = (float)s * inv;
    float cs, sn;
    sincosf(freq, &sn, &cs);
    tab[idx*2+0] = cs;
    tab[idx*2+1] = sn;
}

// ==================== head assembly + RoPE ====================
__global__ void assemble_q_kernel(const float* __restrict__ qc,
                                  const float* __restrict__ qr,
                                  const float* __restrict__ tab,
                                  float* __restrict__ q)
{
    int idx = blockIdx.x * blockDim.x + threadIdx.x;
    if (idx >= MM*HID) return;
    int d = idx & 127;
    int h = (idx >> 7) & 15;
    int t = idx >> 11;
    int s = t & (SS - 1);
    float val;
    if (d < CC) {
        val = qc[(long)t * (CC*NH) + h*CC + d];
    } else {
        int r = d - CC;
        int i = r & 15;
        float cs = tab[(s*16+i)*2+0];
        float sn = tab[(s*16+i)*2+1];
        const float* base = qr + (long)t * (RR*NH) + h*RR;
        float x = base[r];
        float xr = (r < 16) ? -base[r + 16] : base[r - 16];
        val = x * cs + xr * sn;
    }
    q[idx] = val;
}

__global__ void assemble_k_kernel(const float* __restrict__ kc,
                                  const float* __restrict__ kr,
                                  const float* __restrict__ tab,
                                  float* __restrict__ k)
{
    int idx = blockIdx.x * blockDim.x + threadIdx.x;
    if (idx >= MM*HID) return;
    int d = idx & 127;
    int h = (idx >> 7) & 15;
    int t = idx >> 11;
    int s = t & (SS - 1);
    float val;
    if (d < CC) {
        val = kc[(long)t * (CC*NH) + h*CC + d];
    } else {
        int r = d - CC;
        int i = r & 15;
        float cs = tab[(s*16+i)*2+0];
        float sn = tab[(s*16+i)*2+1];
        const float* base = kr + (long)t * RR;
        float x = base[r];
        float xr = (r < 16) ? -base[r + 16] : base[r - 16];
        val = x * cs + xr * sn;
    }
    k[idx] = val;
}

// ==================== Flash attention (causal, f32x2) ====================
#define KST 132
#define PST 65

__global__ __launch_bounds__(256) void flash_kernel(
    const float* __restrict__ Q, const float* __restrict__ Kt,
    const float* __restrict__ Vt, float* __restrict__ O)
{
    extern __shared__ float sm[];
    float* Qs = sm;
    float* Ks = Qs + 64*128;
    float* Vs = Ks + 64*KST;
    float* Ps = Vs + 64*KST;

    const int qb = blockIdx.x;
    const int h  = blockIdx.y;
    const int b  = blockIdx.z;
    const int tid = threadIdx.x;
    const int tx = tid & 7;
    const int ty = tid >> 3;
    const int RS = NH * DH;
    const long base = ((long)b * SS * NH + h) * DH;

    {
        const float* src = Q + base + (long)(qb * 64) * RS;
#pragma unroll
        for (int i = 0; i < 8; i++) {
            int idx = tid + i * 256;
            int r = idx >> 5, c = (idx & 31) << 2;
            *(float4*)(Qs + r * 128 + c) = *(const float4*)(src + (long)r * RS + c);
        }
    }

    float m[2], l[2];
    ull acc[2][8];
#pragma unroll
    for (int rr = 0; rr < 2; rr++) {
        m[rr] = -1e30f; l[rr] = 0.f;
#pragma unroll
        for (int p = 0; p < 8; p++) acc[rr][p] = 0ull;
    }
    const float scale = 0.08838834764831845f;

    for (int kb = 0; kb <= qb; kb++) {
        const float* ksrc = Kt + base + (long)(kb * 64) * RS;
        const float* vsrc = Vt + base + (long)(kb * 64) * RS;
        __syncthreads();
#pragma unroll
        for (int i = 0; i < 8; i++) {
            int idx = tid + i * 256;
            int r = idx >> 5, c = (idx & 31) << 2;
            *(float4*)(Ks + r * KST + c) = *(const float4*)(ksrc + (long)r * RS + c);
            *(float4*)(Vs + r * KST + c) = *(const float4*)(vsrc + (long)r * RS + c);
        }
        __syncthreads();

        ull s2[2][8];
#pragma unroll
        for (int rr = 0; rr < 2; rr++)
#pragma unroll
            for (int j = 0; j < 8; j++) s2[rr][j] = 0ull;

        for (int d = 0; d < 128; d += 4) {
            ulonglong2 q0 = *(const ulonglong2*)(Qs + (ty*2+0)*128 + d);
            ulonglong2 q1 = *(const ulonglong2*)(Qs + (ty*2+1)*128 + d);
#pragma unroll
            for (int j = 0; j < 8; j++) {
                ulonglong2 kq = *(const ulonglong2*)(Ks + (j*8+tx)*KST + d);
                fma2(s2[0][j], q0.x, kq.x);
                fma2(s2[0][j], q0.y, kq.y);
                fma2(s2[1][j], q1.x, kq.x);
                fma2(s2[1][j], q1.y, kq.y);
            }
        }

        float s[2][8];
#pragma unroll
        for (int rr = 0; rr < 2; rr++)
#pragma unroll
            for (int j = 0; j < 8; j++) {
                float2 t2 = unpack2(s2[rr][j]);
                s[rr][j] = (t2.x + t2.y) * scale;
            }

        if (kb == qb) {
#pragma unroll
            for (int rr = 0; rr < 2; rr++) {
                int qrow = qb*64 + ty*2 + rr;
#pragma unroll
                for (int j = 0; j < 8; j++) {
                    int kcol = kb*64 + j*8 + tx;
                    if (kcol > qrow) s[rr][j] = -10000.0f;
                }
            }
        }

#pragma unroll
        for (int rr = 0; rr < 2; rr++) {
            float mx = s[rr][0];
#pragma unroll
            for (int j = 1; j < 8; j++) mx = fmaxf(mx, s[rr][j]);
            mx = fmaxf(mx, __shfl_xor_sync(0xffffffffu, mx, 1));
            mx = fmaxf(mx, __shfl_xor_sync(0xffffffffu, mx, 2));
            mx = fmaxf(mx, __shfl_xor_sync(0xffffffffu, mx, 4));
            float mnew = fmaxf(m[rr], mx);
            float alpha = __expf(m[rr] - mnew);
            float sum = 0.f;
#pragma unroll
            for (int j = 0; j < 8; j++) {
                float p = __expf(s[rr][j] - mnew);
                s[rr][j] = p;
                sum += p;
            }
            sum += __shfl_xor_sync(0xffffffffu, sum, 1);
            sum += __shfl_xor_sync(0xffffffffu, sum, 2);
            sum += __shfl_xor_sync(0xffffffffu, sum, 4);
            l[rr] = l[rr] * alpha + sum;
            m[rr] = mnew;
            ull al = dup2(alpha);
#pragma unroll
            for (int p = 0; p < 8; p++) mul2(acc[rr][p], al);
        }

#pragma unroll
        for (int rr = 0; rr < 2; rr++)
#pragma unroll
            for (int j = 0; j < 8; j++)
                Ps[(ty*2+rr)*PST + j*8 + tx] = s[rr][j];
        __syncthreads();

        for (int k = 0; k < 64; k++) {
            ull p0 = dup2(Ps[(ty*2+0)*PST + k]);
            ull p1 = dup2(Ps[(ty*2+1)*PST + k]);
#pragma unroll
            for (int p = 0; p < 8; p++) {
                ull v2 = *(const ull*)(Vs + k*KST + tx*2 + p*16);
                fma2(acc[0][p], p0, v2);
                fma2(acc[1][p], p1, v2);
            }
        }
    }

#pragma unroll
    for (int rr = 0; rr < 2; rr++) {
        int row = qb*64 + ty*2 + rr;
        ull iv = dup2(1.0f / l[rr]);
#pragma unroll
        for (int p = 0; p < 8; p++) {
            mul2(acc[rr][p], iv);
            *(ull*)(&O[base + (long)row * RS + tx*2 + p*16]) = acc[rr][p];
        }
    }
}

// ==================== launcher ====================
static inline void launch_gemm(const float* A, const float* W, const float* bias,
                               float* C, int M, int N, int K)
{
    if (N % 128 == 0) {
        dim3 grid(N / 128, M / 128);
        mma_gemm_kernel<128, 2, 4><<<grid, 256>>>(A, W, bias, C, M, N, K);
    } else {
        dim3 grid(N / 32, M / 128);
        mma_gemm_kernel<32, 8, 1><<<grid, 256>>>(A, W, bias, C, M, N, K);
    }
}

extern "C" void kernel_launch(void* const* d_in, const int* in_sizes, int n_in,
                              void* d_out, int out_size)
{
    const float* x       = (const float*)d_in[0];
    const float* Wq_down = (const float*)d_in[1];
    const float* Wq_up   = (const float*)d_in[2];
    const float* Wq_rope = (const float*)d_in[3];
    const float* Wkv_down= (const float*)d_in[4];
    const float* Wk_up   = (const float*)d_in[5];
    const float* Wk_rope = (const float*)d_in[6];
    const float* Wv_up   = (const float*)d_in[7];
    const float* Wo      = (const float*)d_in[8];
    const float* bo      = (const float*)d_in[9];
    float* out = (float*)d_out;

    float *qlat, *kvlat, *qc, *qr, *kc, *kr, *v, *q, *k, *ctx, *tab;
    cudaGetSymbolAddress((void**)&qlat,  g_qlat);
    cudaGetSymbolAddress((void**)&kvlat, g_kvlat);
    cudaGetSymbolAddress((void**)&qc,    g_qc);
    cudaGetSymbolAddress((void**)&qr,    g_qr);
    cudaGetSymbolAddress((void**)&kc,    g_kc);
    cudaGetSymbolAddress((void**)&kr,    g_kr);
    cudaGetSymbolAddress((void**)&v,     g_v);
    cudaGetSymbolAddress((void**)&q,     g_q);
    cudaGetSymbolAddress((void**)&k,     g_k);
    cudaGetSymbolAddress((void**)&ctx,   g_ctx);
    cudaGetSymbolAddress((void**)&tab,   g_rope);

    rope_table_kernel<<<(SS*16 + 255)/256, 256>>>(tab);

    // projections (tensor-core bf16 3-pass)
    launch_gemm(x,     Wq_down,  nullptr, qlat,  MM, LAT,   HID);
    launch_gemm(x,     Wkv_down, nullptr, kvlat, MM, LAT,   HID);
    launch_gemm(x,     Wk_rope,  nullptr, kr,    MM, RR,    HID);
    launch_gemm(qlat,  Wq_up,    nullptr, qc,    MM, CC*NH, LAT);
    launch_gemm(qlat,  Wq_rope,  nullptr, qr,    MM, RR*NH, LAT);
    launch_gemm(kvlat, Wk_up,    nullptr, kc,    MM, CC*NH, LAT);
    launch_gemm(kvlat, Wv_up,    nullptr, v,     MM, HID,   LAT);

    // rope + head assembly
    {
        int total = MM * HID;
        int threads = 256;
        int blocks = (total + threads - 1) / threads;
        assemble_q_kernel<<<blocks, threads>>>(qc, qr, tab, q);
        assemble_k_kernel<<<blocks, threads>>>(kc, kr, tab, k);
    }

    // flash attention
    {
        size_t smem = (size_t)(64*128 + 64*KST + 64*KST + 64*PST) * sizeof(float);
        cudaFuncSetAttribute(flash_kernel,
                             cudaFuncAttributeMaxDynamicSharedMemorySize, (int)smem);
        dim3 grid(SS / 64, NH, BB);
        flash_kernel<<<grid, 256, smem>>>(q, k, v, ctx);
    }

    // output projection + bias
    launch_gemm(ctx, Wo, bo, out, MM, HID, HID);
}

// round 7
// speedup vs baseline: 1.9395x; 1.2342x over previous
#include <cuda_runtime.h>
#include <cuda_bf16.h>
#include <math.h>
#include <stdint.h>

// Problem constants
#define HID 2048
#define NH  16
#define LAT 512
#define RR  32
#define DH  128
#define CC  96
#define BB  2
#define SS  2048
#define MM  (BB*SS)   // 4096

typedef unsigned long long ull;

// ---------------- bf16 mma.sync helpers ----------------
__device__ __forceinline__ void mma16816(float* c, const uint32_t* a, const uint32_t* b) {
    asm volatile(
        "mma.sync.aligned.m16n8k16.row.col.f32.bf16.bf16.f32 "
        "{%0,%1,%2,%3}, {%4,%5,%6,%7}, {%8,%9}, {%0,%1,%2,%3};"
        : "+f"(c[0]), "+f"(c[1]), "+f"(c[2]), "+f"(c[3])
        : "r"(a[0]), "r"(a[1]), "r"(a[2]), "r"(a[3]), "r"(b[0]), "r"(b[1]));
}

// split fp32 -> hi/lo bf16 pair (a ~= hi + lo)
__device__ __forceinline__ void split_bf16(float x, __nv_bfloat16& h, __nv_bfloat16& l) {
    h = __float2bfloat16_rn(x);
    l = __float2bfloat16_rn(x - __bfloat162float(h));
}
__device__ __forceinline__ uint32_t pack_bf16(float lo, float hi) {
    __nv_bfloat162 t(__float2bfloat16_rn(lo), __float2bfloat16_rn(hi));
    return *(uint32_t*)&t;
}
__device__ __forceinline__ float bf16f(__nv_bfloat16 x) { return __bfloat162float(x); }

// -------- scratch (device globals; no runtime allocation) --------
__device__ float g_qlat [MM*LAT];
__device__ float g_kvlat[MM*LAT];
__device__ float g_qc   [MM*(CC*NH)];
__device__ float g_qr   [MM*(RR*NH)];
__device__ float g_kc   [MM*(CC*NH)];
__device__ float g_kr   [MM*RR];
__device__ float g_v    [MM*HID];
__device__ float g_q    [MM*HID];
__device__ float g_k    [MM*HID];
__device__ float g_ctx  [MM*HID];
__device__ float g_rope [SS*16*2];

// ==================== mma.sync bf16 3-pass GEMM ====================
// C[M,N] = A[M,K] @ W[N,K]^T (+bias). BK=32.
template<int BM, int BN, int WARPS_M, int WARPS_N>
__global__ __launch_bounds__(256) void mma_gemm_kernel(
    const float* __restrict__ A, const float* __restrict__ W,
    const float* __restrict__ bias, float* __restrict__ C,
    int M, int N, int K)
{
    constexpr int BK = 32, ST = 40;
    constexpr int WTM = BM / WARPS_M;
    constexpr int WTN = BN / WARPS_N;
    constexpr int MT = WTM / 16;
    constexpr int NT = WTN / 8;

    __shared__ __nv_bfloat16 Ah[BM*ST], Al[BM*ST], Bh[BN*ST], Bl[BN*ST];

    const int bm = blockIdx.y * BM;
    const int bn = blockIdx.x * BN;
    const int tid = threadIdx.x;
    const int wid = tid >> 5;
    const int lane = tid & 31;
    const int wm = wid / WARPS_N;
    const int wn = wid % WARPS_N;
    const int g = lane >> 2;
    const int tig = lane & 3;

    float acc[MT][NT][4];
#pragma unroll
    for (int mt = 0; mt < MT; mt++)
#pragma unroll
        for (int nt = 0; nt < NT; nt++)
#pragma unroll
            for (int i = 0; i < 4; i++) acc[mt][nt][i] = 0.f;

    for (int k0 = 0; k0 < K; k0 += BK) {
#pragma unroll
        for (int it = 0; it < BM*BK/4/256; it++) {
            int f = tid + it * 256;
            int row = f >> 3, cg = f & 7;
            float4 v = *(const float4*)(A + (long)(bm + row) * K + k0 + cg * 4);
            __nv_bfloat16 hx, lx, hy, ly, hz, lz, hw, lw;
            split_bf16(v.x, hx, lx); split_bf16(v.y, hy, ly);
            split_bf16(v.z, hz, lz); split_bf16(v.w, hw, lw);
            __nv_bfloat162* ph = (__nv_bfloat162*)&Ah[row*ST + cg*4];
            __nv_bfloat162* pl = (__nv_bfloat162*)&Al[row*ST + cg*4];
            ph[0] = __nv_bfloat162(hx, hy); ph[1] = __nv_bfloat162(hz, hw);
            pl[0] = __nv_bfloat162(lx, ly); pl[1] = __nv_bfloat162(lz, lw);
        }
#pragma unroll
        for (int it = 0; it < BN*BK/4/256; it++) {
            int f = tid + it * 256;
            int row = f >> 3, cg = f & 7;
            float4 v = *(const float4*)(W + (long)(bn + row) * K + k0 + cg * 4);
            __nv_bfloat16 hx, lx, hy, ly, hz, lz, hw, lw;
            split_bf16(v.x, hx, lx); split_bf16(v.y, hy, ly);
            split_bf16(v.z, hz, lz); split_bf16(v.w, hw, lw);
            __nv_bfloat162* ph = (__nv_bfloat162*)&Bh[row*ST + cg*4];
            __nv_bfloat162* pl = (__nv_bfloat162*)&Bl[row*ST + cg*4];
            ph[0] = __nv_bfloat162(hx, hy); ph[1] = __nv_bfloat162(hz, hw);
            pl[0] = __nv_bfloat162(lx, ly); pl[1] = __nv_bfloat162(lz, lw);
        }
        __syncthreads();

#pragma unroll
        for (int kk = 0; kk < BK; kk += 16) {
            uint32_t afh[MT][4], afl[MT][4], bfh[NT][2], bfl[NT][2];
#pragma unroll
            for (int mt = 0; mt < MT; mt++) {
                int rb = wm * WTM + mt * 16;
                int a0 = (rb + g) * ST + kk + tig * 2;
                int a1 = (rb + g + 8) * ST + kk + tig * 2;
                afh[mt][0] = *(const uint32_t*)&Ah[a0];
                afh[mt][1] = *(const uint32_t*)&Ah[a1];
                afh[mt][2] = *(const uint32_t*)&Ah[a0 + 8];
                afh[mt][3] = *(const uint32_t*)&Ah[a1 + 8];
                afl[mt][0] = *(const uint32_t*)&Al[a0];
                afl[mt][1] = *(const uint32_t*)&Al[a1];
                afl[mt][2] = *(const uint32_t*)&Al[a0 + 8];
                afl[mt][3] = *(const uint32_t*)&Al[a1 + 8];
            }
#pragma unroll
            for (int nt = 0; nt < NT; nt++) {
                int nb = wn * WTN + nt * 8;
                int b0 = (nb + g) * ST + kk + tig * 2;
                bfh[nt][0] = *(const uint32_t*)&Bh[b0];
                bfh[nt][1] = *(const uint32_t*)&Bh[b0 + 8];
                bfl[nt][0] = *(const uint32_t*)&Bl[b0];
                bfl[nt][1] = *(const uint32_t*)&Bl[b0 + 8];
            }
#pragma unroll
            for (int mt = 0; mt < MT; mt++)
#pragma unroll
                for (int nt = 0; nt < NT; nt++) {
                    mma16816(acc[mt][nt], afh[mt], bfh[nt]);
                    mma16816(acc[mt][nt], afh[mt], bfl[nt]);
                    mma16816(acc[mt][nt], afl[mt], bfh[nt]);
                }
        }
        __syncthreads();
    }

#pragma unroll
    for (int mt = 0; mt < MT; mt++) {
        int row0 = bm + wm * WTM + mt * 16 + g;
#pragma unroll
        for (int nt = 0; nt < NT; nt++) {
            int col = bn + wn * WTN + nt * 8 + tig * 2;
            float b0 = bias ? bias[col] : 0.f;
            float b1 = bias ? bias[col + 1] : 0.f;
            float2 v0 = make_float2(acc[mt][nt][0] + b0, acc[mt][nt][1] + b1);
            float2 v1 = make_float2(acc[mt][nt][2] + b0, acc[mt][nt][3] + b1);
            *(float2*)&C[(long)row0 * N + col]       = v0;
            *(float2*)&C[(long)(row0 + 8) * N + col] = v1;
        }
    }
}

// ==================== RoPE table ====================
__global__ void rope_table_kernel(float* __restrict__ tab)
{
    int idx = blockIdx.x * blockDim.x + threadIdx.x;
    if (idx >= SS * 16) return;
    int i = idx & 15;
    int s = idx >> 4;
    float inv = powf(10000.0f, -(float)i / 16.0f);
    float freq = (float)s * inv;
    float cs, sn;
    sincosf(freq, &sn, &cs);
    tab[idx*2+0] = cs;
    tab[idx*2+1] = sn;
}

// ==================== head assembly + RoPE ====================
__global__ void assemble_q_kernel(const float* __restrict__ qc,
                                  const float* __restrict__ qr,
                                  const float* __restrict__ tab,
                                  float* __restrict__ q)
{
    int idx = blockIdx.x * blockDim.x + threadIdx.x;
    if (idx >= MM*HID) return;
    int d = idx & 127;
    int h = (idx >> 7) & 15;
    int t = idx >> 11;
    int s = t & (SS - 1);
    float val;
    if (d < CC) {
        val = qc[(long)t * (CC*NH) + h*CC + d];
    } else {
        int r = d - CC;
        int i = r & 15;
        float cs = tab[(s*16+i)*2+0];
        float sn = tab[(s*16+i)*2+1];
        const float* base = qr + (long)t * (RR*NH) + h*RR;
        float x = base[r];
        float xr = (r < 16) ? -base[r + 16] : base[r - 16];
        val = x * cs + xr * sn;
    }
    q[idx] = val;
}

__global__ void assemble_k_kernel(const float* __restrict__ kc,
                                  const float* __restrict__ kr,
                                  const float* __restrict__ tab,
                                  float* __restrict__ k)
{
    int idx = blockIdx.x * blockDim.x + threadIdx.x;
    if (idx >= MM*HID) return;
    int d = idx & 127;
    int h = (idx >> 7) & 15;
    int t = idx >> 11;
    int s = t & (SS - 1);
    float val;
    if (d < CC) {
        val = kc[(long)t * (CC*NH) + h*CC + d];
    } else {
        int r = d - CC;
        int i = r & 15;
        float cs = tab[(s*16+i)*2+0];
        float sn = tab[(s*16+i)*2+1];
        const float* base = kr + (long)t * RR;
        float x = base[r];
        float xr = (r < 16) ? -base[r + 16] : base[r - 16];
        val = x * cs + xr * sn;
    }
    k[idx] = val;
}

// ==================== Flash attention (causal, bf16 mma 3-pass) ====================
// 64 q-rows x 64 k-rows per tile, D=128. 128 threads (4 warps), warp w owns
// q rows w*16..w*16+15. S kept in mma C fragments; P converted to A fragments
// in registers (C-frag (g,2tig) layout == A-frag layout). V staged transposed.
#define QST 136   // Q/K smem bf16 row stride
#define VST 72    // Vt smem bf16 row stride (row = d, col = token)

__global__ __launch_bounds__(128) void flash_mma_kernel(
    const float* __restrict__ Q, const float* __restrict__ Kt,
    const float* __restrict__ Vt, float* __restrict__ O)
{
    extern __shared__ __nv_bfloat16 smf[];
    __nv_bfloat16* Qh = smf;                 // 64*QST
    __nv_bfloat16* Ql = Qh + 64*QST;
    __nv_bfloat16* Kh = Ql + 64*QST;
    __nv_bfloat16* Kl = Kh + 64*QST;
    __nv_bfloat16* Vh = Kl + 64*QST;         // 128*VST (transposed: [d][t])
    __nv_bfloat16* Vl = Vh + 128*VST;

    const int qb = blockIdx.x;
    const int h  = blockIdx.y;
    const int b  = blockIdx.z;
    const int tid = threadIdx.x;
    const int w = tid >> 5;
    const int lane = tid & 31;
    const int g = lane >> 2;
    const int tig = lane & 3;
    const int RS = NH * DH;
    const long base = ((long)b * SS * NH + h) * DH;
    const float scale = 0.08838834764831845f;  // 1/sqrt(128)

    // ---- load Q tile (64 x 128) and split ----
    {
        const float* src = Q + base + (long)(qb * 64) * RS;
#pragma unroll
        for (int it = 0; it < 16; it++) {
            int f = tid + it * 128;
            int row = f >> 5, c = (f & 31) << 2;
            float4 v = *(const float4*)(src + (long)row * RS + c);
            __nv_bfloat16 hx, lx, hy, ly, hz, lz, hw, lw;
            split_bf16(v.x, hx, lx); split_bf16(v.y, hy, ly);
            split_bf16(v.z, hz, lz); split_bf16(v.w, hw, lw);
            __nv_bfloat162* ph = (__nv_bfloat162*)&Qh[row*QST + c];
            __nv_bfloat162* pl = (__nv_bfloat162*)&Ql[row*QST + c];
            ph[0] = __nv_bfloat162(hx, hy); ph[1] = __nv_bfloat162(hz, hw);
            pl[0] = __nv_bfloat162(lx, ly); pl[1] = __nv_bfloat162(lz, lw);
        }
    }

    float m0 = -1e30f, m8 = -1e30f, l0 = 0.f, l8 = 0.f;
    float o[16][4];
#pragma unroll
    for (int nd = 0; nd < 16; nd++)
#pragma unroll
        for (int i = 0; i < 4; i++) o[nd][i] = 0.f;

    for (int kb = 0; kb <= qb; kb++) {
        const float* ksrc = Kt + base + (long)(kb * 64) * RS;
        const float* vsrc = Vt + base + (long)(kb * 64) * RS;
        __syncthreads();
        // K: row-major split
#pragma unroll
        for (int it = 0; it < 16; it++) {
            int f = tid + it * 128;
            int row = f >> 5, c = (f & 31) << 2;
            float4 v = *(const float4*)(ksrc + (long)row * RS + c);
            __nv_bfloat16 hx, lx, hy, ly, hz, lz, hw, lw;
            split_bf16(v.x, hx, lx); split_bf16(v.y, hy, ly);
            split_bf16(v.z, hz, lz); split_bf16(v.w, hw, lw);
            __nv_bfloat162* ph = (__nv_bfloat162*)&Kh[row*QST + c];
            __nv_bfloat162* pl = (__nv_bfloat162*)&Kl[row*QST + c];
            ph[0] = __nv_bfloat162(hx, hy); ph[1] = __nv_bfloat162(hz, hw);
            pl[0] = __nv_bfloat162(lx, ly); pl[1] = __nv_bfloat162(lz, lw);
        }
        // V: transposed split store Vt[d][t]
#pragma unroll
        for (int it = 0; it < 16; it++) {
            int f = tid + it * 128;
            int row = f >> 5, c = (f & 31) << 2;   // row = token, c = d base
            float4 v = *(const float4*)(vsrc + (long)row * RS + c);
            __nv_bfloat16 hh, llo;
            split_bf16(v.x, hh, llo); Vh[(c+0)*VST + row] = hh; Vl[(c+0)*VST + row] = llo;
            split_bf16(v.y, hh, llo); Vh[(c+1)*VST + row] = hh; Vl[(c+1)*VST + row] = llo;
            split_bf16(v.z, hh, llo); Vh[(c+2)*VST + row] = hh; Vl[(c+2)*VST + row] = llo;
            split_bf16(v.w, hh, llo); Vh[(c+3)*VST + row] = hh; Vl[(c+3)*VST + row] = llo;
        }
        __syncthreads();

        // ---- S = Q K^T (16 x 64 per warp), 3-pass ----
        float sc[8][4];
#pragma unroll
        for (int nt = 0; nt < 8; nt++)
#pragma unroll
            for (int i = 0; i < 4; i++) sc[nt][i] = 0.f;

#pragma unroll
        for (int kk = 0; kk < 128; kk += 16) {
            uint32_t ah[4], al[4];
            int a0 = (w*16 + g) * QST + kk + tig*2;
            int a1 = (w*16 + g + 8) * QST + kk + tig*2;
            ah[0] = *(const uint32_t*)&Qh[a0];
            ah[1] = *(const uint32_t*)&Qh[a1];
            ah[2] = *(const uint32_t*)&Qh[a0 + 8];
            ah[3] = *(const uint32_t*)&Qh[a1 + 8];
            al[0] = *(const uint32_t*)&Ql[a0];
            al[1] = *(const uint32_t*)&Ql[a1];
            al[2] = *(const uint32_t*)&Ql[a0 + 8];
            al[3] = *(const uint32_t*)&Ql[a1 + 8];
#pragma unroll
            for (int nt = 0; nt < 8; nt++) {
                uint32_t bh[2], bl[2];
                int b0 = (nt*8 + g) * QST + kk + tig*2;
                bh[0] = *(const uint32_t*)&Kh[b0];
                bh[1] = *(const uint32_t*)&Kh[b0 + 8];
                bl[0] = *(const uint32_t*)&Kl[b0];
                bl[1] = *(const uint32_t*)&Kl[b0 + 8];
                mma16816(sc[nt], ah, bh);
                mma16816(sc[nt], ah, bl);
                mma16816(sc[nt], al, bh);
            }
        }

        // scale + causal mask
#pragma unroll
        for (int nt = 0; nt < 8; nt++)
#pragma unroll
            for (int i = 0; i < 4; i++) sc[nt][i] *= scale;
        if (kb == qb) {
            int row0 = qb*64 + w*16 + g;
#pragma unroll
            for (int nt = 0; nt < 8; nt++) {
                int col = kb*64 + nt*8 + tig*2;
                if (col     > row0)     sc[nt][0] = -1e30f;
                if (col + 1 > row0)     sc[nt][1] = -1e30f;
                if (col     > row0 + 8) sc[nt][2] = -1e30f;
                if (col + 1 > row0 + 8) sc[nt][3] = -1e30f;
            }
        }

        // ---- online softmax (rows g and g+8) ----
        float r0 = -1e30f, r8 = -1e30f;
#pragma unroll
        for (int nt = 0; nt < 8; nt++) {
            r0 = fmaxf(r0, fmaxf(sc[nt][0], sc[nt][1]));
            r8 = fmaxf(r8, fmaxf(sc[nt][2], sc[nt][3]));
        }
        r0 = fmaxf(r0, __shfl_xor_sync(0xffffffffu, r0, 1));
        r0 = fmaxf(r0, __shfl_xor_sync(0xffffffffu, r0, 2));
        r8 = fmaxf(r8, __shfl_xor_sync(0xffffffffu, r8, 1));
        r8 = fmaxf(r8, __shfl_xor_sync(0xffffffffu, r8, 2));
        float mn0 = fmaxf(m0, r0), mn8 = fmaxf(m8, r8);
        float alpha0 = __expf(m0 - mn0), alpha8 = __expf(m8 - mn8);
        float s0 = 0.f, s8 = 0.f;
#pragma unroll
        for (int nt = 0; nt < 8; nt++) {
            sc[nt][0] = __expf(sc[nt][0] - mn0);
            sc[nt][1] = __expf(sc[nt][1] - mn0);
            sc[nt][2] = __expf(sc[nt][2] - mn8);
            sc[nt][3] = __expf(sc[nt][3] - mn8);
            s0 += sc[nt][0] + sc[nt][1];
            s8 += sc[nt][2] + sc[nt][3];
        }
        s0 += __shfl_xor_sync(0xffffffffu, s0, 1);
        s0 += __shfl_xor_sync(0xffffffffu, s0, 2);
        s8 += __shfl_xor_sync(0xffffffffu, s8, 1);
        s8 += __shfl_xor_sync(0xffffffffu, s8, 2);
        l0 = l0 * alpha0 + s0; l8 = l8 * alpha8 + s8;
        m0 = mn0; m8 = mn8;
#pragma unroll
        for (int nd = 0; nd < 16; nd++) {
            o[nd][0] *= alpha0; o[nd][1] *= alpha0;
            o[nd][2] *= alpha8; o[nd][3] *= alpha8;
        }

        // ---- O += P V (3-pass, P built from C-frags in registers) ----
#pragma unroll
        for (int t = 0; t < 4; t++) {
            uint32_t ph[4], pl[4];
            {
                float p00 = sc[2*t][0],   p01 = sc[2*t][1];
                float p02 = sc[2*t][2],   p03 = sc[2*t][3];
                float p10 = sc[2*t+1][0], p11 = sc[2*t+1][1];
                float p12 = sc[2*t+1][2], p13 = sc[2*t+1][3];
                ph[0] = pack_bf16(p00, p01);
                ph[1] = pack_bf16(p02, p03);
                ph[2] = pack_bf16(p10, p11);
                ph[3] = pack_bf16(p12, p13);
                __nv_bfloat162 h;
                h = *(__nv_bfloat162*)&ph[0];
                pl[0] = pack_bf16(p00 - bf16f(h.x), p01 - bf16f(h.y));
                h = *(__nv_bfloat162*)&ph[1];
                pl[1] = pack_bf16(p02 - bf16f(h.x), p03 - bf16f(h.y));
                h = *(__nv_bfloat162*)&ph[2];
                pl[2] = pack_bf16(p10 - bf16f(h.x), p11 - bf16f(h.y));
                h = *(__nv_bfloat162*)&ph[3];
                pl[3] = pack_bf16(p12 - bf16f(h.x), p13 - bf16f(h.y));
            }
#pragma unroll
            for (int nd = 0; nd < 16; nd++) {
                uint32_t vh[2], vl[2];
                int b0 = (nd*8 + g) * VST + t*16 + tig*2;
                vh[0] = *(const uint32_t*)&Vh[b0];
                vh[1] = *(const uint32_t*)&Vh[b0 + 8];
                vl[0] = *(const uint32_t*)&Vl[b0];
                vl[1] = *(const uint32_t*)&Vl[b0 + 8];
                mma16816(o[nd], ph, vh);
                mma16816(o[nd], ph, vl);
                mma16816(o[nd], pl, vh);
            }
        }
    }

    // ---- write out ----
    {
        float inv0 = 1.0f / l0, inv8 = 1.0f / l8;
        int row0 = qb*64 + w*16 + g;
        float* dst0 = O + base + (long)row0 * RS;
        float* dst8 = O + base + (long)(row0 + 8) * RS;
#pragma unroll
        for (int nd = 0; nd < 16; nd++) {
            int col = nd*8 + tig*2;
            *(float2*)(dst0 + col) = make_float2(o[nd][0] * inv0, o[nd][1] * inv0);
            *(float2*)(dst8 + col) = make_float2(o[nd][2] * inv8, o[nd][3] * inv8);
        }
    }
}

// ==================== launcher ====================
static inline void launch_gemm(const float* A, const float* W, const float* bias,
                               float* C, int M, int N, int K)
{
    if (N % 128 == 0) {
        dim3 grid(N / 128, M / 128);
        mma_gemm_kernel<128, 128, 2, 4><<<grid, 256>>>(A, W, bias, C, M, N, K);
    } else {
        dim3 grid(N / 32, M / 32);
        mma_gemm_kernel<32, 32, 2, 4><<<grid, 256>>>(A, W, bias, C, M, N, K);
    }
}

extern "C" void kernel_launch(void* const* d_in, const int* in_sizes, int n_in,
                              void* d_out, int out_size)
{
    const float* x       = (const float*)d_in[0];
    const float* Wq_down = (const float*)d_in[1];
    const float* Wq_up   = (const float*)d_in[2];
    const float* Wq_rope = (const float*)d_in[3];
    const float* Wkv_down= (const float*)d_in[4];
    const float* Wk_up   = (const float*)d_in[5];
    const float* Wk_rope = (const float*)d_in[6];
    const float* Wv_up   = (const float*)d_in[7];
    const float* Wo      = (const float*)d_in[8];
    const float* bo      = (const float*)d_in[9];
    float* out = (float*)d_out;

    float *qlat, *kvlat, *qc, *qr, *kc, *kr, *v, *q, *k, *ctx, *tab;
    cudaGetSymbolAddress((void**)&qlat,  g_qlat);
    cudaGetSymbolAddress((void**)&kvlat, g_kvlat);
    cudaGetSymbolAddress((void**)&qc,    g_qc);
    cudaGetSymbolAddress((void**)&qr,    g_qr);
    cudaGetSymbolAddress((void**)&kc,    g_kc);
    cudaGetSymbolAddress((void**)&kr,    g_kr);
    cudaGetSymbolAddress((void**)&v,     g_v);
    cudaGetSymbolAddress((void**)&q,     g_q);
    cudaGetSymbolAddress((void**)&k,     g_k);
    cudaGetSymbolAddress((void**)&ctx,   g_ctx);
    cudaGetSymbolAddress((void**)&tab,   g_rope);

    rope_table_kernel<<<(SS*16 + 255)/256, 256>>>(tab);

    // projections (tensor-core bf16 3-pass)
    launch_gemm(x,     Wq_down,  nullptr, qlat,  MM, LAT,   HID);
    launch_gemm(x,     Wkv_down, nullptr, kvlat, MM, LAT,   HID);
    launch_gemm(x,     Wk_rope,  nullptr, kr,    MM, RR,    HID);
    launch_gemm(qlat,  Wq_up,    nullptr, qc,    MM, CC*NH, LAT);
    launch_gemm(qlat,  Wq_rope,  nullptr, qr,    MM, RR*NH, LAT);
    launch_gemm(kvlat, Wk_up,    nullptr, kc,    MM, CC*NH, LAT);
    launch_gemm(kvlat, Wv_up,    nullptr, v,     MM, HID,   LAT);

    // rope + head assembly
    {
        int total = MM * HID;
        int threads = 256;
        int blocks = (total + threads - 1) / threads;
        assemble_q_kernel<<<blocks, threads>>>(qc, qr, tab, q);
        assemble_k_kernel<<<blocks, threads>>>(kc, kr, tab, k);
    }

    // flash attention (bf16 mma 3-pass)
    {
        size_t smem = (size_t)(4*64*QST + 2*128*VST) * sizeof(__nv_bfloat16);
        cudaFuncSetAttribute(flash_mma_kernel,
                             cudaFuncAttributeMaxDynamicSharedMemorySize, (int)smem);
        dim3 grid(SS / 64, NH, BB);
        flash_mma_kernel<<<grid, 128, smem>>>(q, k, v, ctx);
    }

    // output projection + bias
    launch_gemm(ctx, Wo, bo, out, MM, HID, HID);
}

// round 8
// speedup vs baseline: 2.1201x; 1.0931x over previous
#include <cuda_runtime.h>
#include <cuda_bf16.h>
#include <math.h>
#include <stdint.h>

// Problem constants
#define HID 2048
#define NH  16
#define LAT 512
#define RR  32
#define DH  128
#define CC  96
#define BB  2
#define SS  2048
#define MM  (BB*SS)   // 4096

typedef __nv_bfloat16 bf16;

// ---------------- helpers ----------------
__device__ __forceinline__ void mma16816(float* c, const uint32_t* a, const uint32_t* b) {
    asm volatile(
        "mma.sync.aligned.m16n8k16.row.col.f32.bf16.bf16.f32 "
        "{%0,%1,%2,%3}, {%4,%5,%6,%7}, {%8,%9}, {%0,%1,%2,%3};"
        : "+f"(c[0]), "+f"(c[1]), "+f"(c[2]), "+f"(c[3])
        : "r"(a[0]), "r"(a[1]), "r"(a[2]), "r"(a[3]), "r"(b[0]), "r"(b[1]));
}
__device__ __forceinline__ void split_bf16(float x, bf16& h, bf16& l) {
    h = __float2bfloat16_rn(x);
    l = __float2bfloat16_rn(x - __bfloat162float(h));
}
__device__ __forceinline__ uint32_t pack_bf16(float lo, float hi) {
    __nv_bfloat162 t(__float2bfloat16_rn(lo), __float2bfloat16_rn(hi));
    return *(uint32_t*)&t;
}
__device__ __forceinline__ float bf16f(bf16 x) { return __bfloat162float(x); }
__device__ __forceinline__ uint32_t smem_u32(const void* p) {
    uint32_t a;
    asm("{ .reg .u64 t; cvta.to.shared.u64 t, %1; cvt.u32.u64 %0, t; }" : "=r"(a) : "l"(p));
    return a;
}
__device__ __forceinline__ void cp16(void* dst, const void* src) {
    asm volatile("cp.async.cg.shared.global [%0], [%1], 16;"
                 :: "r"(smem_u32(dst)), "l"(src));
}
#define CP_COMMIT() asm volatile("cp.async.commit_group;" ::: "memory")
#define CP_WAIT0()  asm volatile("cp.async.wait_group 0;" ::: "memory")
#define CP_WAIT1()  asm volatile("cp.async.wait_group 1;" ::: "memory")

// -------- scratch (device globals; no runtime allocation) --------
// fp32 intermediates
__device__ float g_qc [MM*(CC*NH)];
__device__ float g_qr [MM*(RR*NH)];
__device__ float g_kc [MM*(CC*NH)];
__device__ float g_kr [MM*RR];
__device__ float g_v  [MM*HID];
__device__ float g_q  [MM*HID];
__device__ float g_k  [MM*HID];
__device__ float g_rope [SS*16*2];
// bf16 hi/lo planes
__device__ bf16 g_xh [MM*HID],  g_xl [MM*HID];
__device__ bf16 g_qlh[MM*LAT],  g_qll[MM*LAT];
__device__ bf16 g_kvh[MM*LAT],  g_kvl[MM*LAT];
__device__ bf16 g_cxh[MM*HID],  g_cxl[MM*HID];
// weight planes
__device__ bf16 g_wqdh[LAT*HID],   g_wqdl[LAT*HID];
__device__ bf16 g_wquh[CC*NH*LAT], g_wqul[CC*NH*LAT];
__device__ bf16 g_wqrh[RR*NH*LAT], g_wqrl[RR*NH*LAT];
__device__ bf16 g_wkdh[LAT*HID],   g_wkdl[LAT*HID];
__device__ bf16 g_wkuh[CC*NH*LAT], g_wkul[CC*NH*LAT];
__device__ bf16 g_wkrh[RR*HID],    g_wkrl[RR*HID];
__device__ bf16 g_wvuh[HID*LAT],   g_wvul[HID*LAT];
__device__ bf16 g_woh [HID*HID],   g_wol [HID*HID];

// ==================== split: fp32 -> bf16 hi/lo planes ====================
__global__ void split_kernel(const float* __restrict__ src,
                             bf16* __restrict__ h, bf16* __restrict__ l, int n)
{
    int i = (blockIdx.x * blockDim.x + threadIdx.x) * 4;
    if (i >= n) return;
    float4 v = *(const float4*)(src + i);
    bf16 hx, lx, hy, ly, hz, lz, hw, lw;
    split_bf16(v.x, hx, lx); split_bf16(v.y, hy, ly);
    split_bf16(v.z, hz, lz); split_bf16(v.w, hw, lw);
    *(__nv_bfloat162*)(h + i)     = __nv_bfloat162(hx, hy);
    *(__nv_bfloat162*)(h + i + 2) = __nv_bfloat162(hz, hw);
    *(__nv_bfloat162*)(l + i)     = __nv_bfloat162(lx, ly);
    *(__nv_bfloat162*)(l + i + 2) = __nv_bfloat162(lz, lw);
}

// ==================== bf16-plane GEMM, cp.async 2-stage pipeline ====================
// C[M,N] = (Ah+Al)[M,K] @ (Bh+Bl)[N,K]^T, 3-pass. Optional fp32 out (+bias) and
// bf16 hi/lo plane out.
template<int BM, int BN, int WARPS_M, int WARPS_N>
__global__ __launch_bounds__(256) void gemm_bf16_kernel(
    const bf16* __restrict__ Ah, const bf16* __restrict__ Al,
    const bf16* __restrict__ Bh, const bf16* __restrict__ Bl,
    const float* __restrict__ bias, float* __restrict__ C,
    bf16* __restrict__ Ch, bf16* __restrict__ Cl,
    int M, int N, int K)
{
    constexpr int BK = 32, ST = 40;
    constexpr int WTM = BM / WARPS_M;
    constexpr int WTN = BN / WARPS_N;
    constexpr int MT = WTM / 16;
    constexpr int NT = WTN / 8;
    constexpr int SSZ = (2*BM + 2*BN) * ST;    // bf16 elems per stage

    extern __shared__ bf16 sm[];

    const int bm = blockIdx.y * BM;
    const int bn = blockIdx.x * BN;
    const int tid = threadIdx.x;
    const int wid = tid >> 5;
    const int lane = tid & 31;
    const int wm = wid / WARPS_N;
    const int wn = wid % WARPS_N;
    const int g = lane >> 2;
    const int tig = lane & 3;

    float acc[MT][NT][4];
#pragma unroll
    for (int mt = 0; mt < MT; mt++)
#pragma unroll
        for (int nt = 0; nt < NT; nt++)
#pragma unroll
            for (int i = 0; i < 4; i++) acc[mt][nt][i] = 0.f;

    const int nc = K / BK;

    // stage loader: chunk -> buffer s
    auto load_stage = [&](int chunk, int s) {
        const long k0 = (long)chunk * BK;
        bf16* stg = sm + s * SSZ;
#pragma unroll
        for (int it = 0; it < (BM*4 + 255) / 256; it++) {
            int f = tid + it * 256;
            if (f < BM*4) {
                int row = f >> 2, cg = f & 3;
                long goff = (long)(bm + row) * K + k0 + cg * 8;
                cp16(stg + row*ST + cg*8, Ah + goff);
                cp16(stg + BM*ST + row*ST + cg*8, Al + goff);
            }
        }
#pragma unroll
        for (int it = 0; it < (BN*4 + 255) / 256; it++) {
            int f = tid + it * 256;
            if (f < BN*4) {
                int row = f >> 2, cg = f & 3;
                long goff = (long)(bn + row) * K + k0 + cg * 8;
                cp16(stg + 2*BM*ST + row*ST + cg*8, Bh + goff);
                cp16(stg + 2*BM*ST + BN*ST + row*ST + cg*8, Bl + goff);
            }
        }
    };

    load_stage(0, 0);
    CP_COMMIT();

    for (int c = 0; c < nc; c++) {
        const int buf = c & 1;
        if (c + 1 < nc) {
            load_stage(c + 1, buf ^ 1);
            CP_COMMIT();
            CP_WAIT1();
        } else {
            CP_WAIT0();
        }
        __syncthreads();

        const bf16* sAh = sm + buf * SSZ;
        const bf16* sAl = sAh + BM*ST;
        const bf16* sBh = sAh + 2*BM*ST;
        const bf16* sBl = sBh + BN*ST;

#pragma unroll
        for (int kk = 0; kk < BK; kk += 16) {
            uint32_t afh[MT][4], afl[MT][4], bfh[NT][2], bfl[NT][2];
#pragma unroll
            for (int mt = 0; mt < MT; mt++) {
                int rb = wm * WTM + mt * 16;
                int a0 = (rb + g) * ST + kk + tig * 2;
                int a1 = (rb + g + 8) * ST + kk + tig * 2;
                afh[mt][0] = *(const uint32_t*)&sAh[a0];
                afh[mt][1] = *(const uint32_t*)&sAh[a1];
                afh[mt][2] = *(const uint32_t*)&sAh[a0 + 8];
                afh[mt][3] = *(const uint32_t*)&sAh[a1 + 8];
                afl[mt][0] = *(const uint32_t*)&sAl[a0];
                afl[mt][1] = *(const uint32_t*)&sAl[a1];
                afl[mt][2] = *(const uint32_t*)&sAl[a0 + 8];
                afl[mt][3] = *(const uint32_t*)&sAl[a1 + 8];
            }
#pragma unroll
            for (int nt = 0; nt < NT; nt++) {
                int nb = wn * WTN + nt * 8;
                int b0 = (nb + g) * ST + kk + tig * 2;
                bfh[nt][0] = *(const uint32_t*)&sBh[b0];
                bfh[nt][1] = *(const uint32_t*)&sBh[b0 + 8];
                bfl[nt][0] = *(const uint32_t*)&sBl[b0];
                bfl[nt][1] = *(const uint32_t*)&sBl[b0 + 8];
            }
#pragma unroll
            for (int mt = 0; mt < MT; mt++)
#pragma unroll
                for (int nt = 0; nt < NT; nt++) {
                    mma16816(acc[mt][nt], afh[mt], bfh[nt]);
                    mma16816(acc[mt][nt], afh[mt], bfl[nt]);
                    mma16816(acc[mt][nt], afl[mt], bfh[nt]);
                }
        }
        __syncthreads();
    }

    // ---- epilogue ----
#pragma unroll
    for (int mt = 0; mt < MT; mt++) {
        int row0 = bm + wm * WTM + mt * 16 + g;
#pragma unroll
        for (int nt = 0; nt < NT; nt++) {
            int col = bn + wn * WTN + nt * 8 + tig * 2;
            float b0 = bias ? bias[col] : 0.f;
            float b1 = bias ? bias[col + 1] : 0.f;
            float v00 = acc[mt][nt][0] + b0, v01 = acc[mt][nt][1] + b1;
            float v10 = acc[mt][nt][2] + b0, v11 = acc[mt][nt][3] + b1;
            long i0 = (long)row0 * N + col;
            long i1 = (long)(row0 + 8) * N + col;
            if (C) {
                *(float2*)&C[i0] = make_float2(v00, v01);
                *(float2*)&C[i1] = make_float2(v10, v11);
            }
            if (Ch) {
                bf16 h, l;
                split_bf16(v00, h, l); Ch[i0]   = h; Cl[i0]   = l;
                split_bf16(v01, h, l); Ch[i0+1] = h; Cl[i0+1] = l;
                split_bf16(v10, h, l); Ch[i1]   = h; Cl[i1]   = l;
                split_bf16(v11, h, l); Ch[i1+1] = h; Cl[i1+1] = l;
            }
        }
    }
}

// ==================== RoPE table ====================
__global__ void rope_table_kernel(float* __restrict__ tab)
{
    int idx = blockIdx.x * blockDim.x + threadIdx.x;
    if (idx >= SS * 16) return;
    int i = idx & 15;
    int s = idx >> 4;
    float inv = powf(10000.0f, -(float)i / 16.0f);
    float freq = (float)s * inv;
    float cs, sn;
    sincosf(freq, &sn, &cs);
    tab[idx*2+0] = cs;
    tab[idx*2+1] = sn;
}

// ==================== head assembly + RoPE ====================
__global__ void assemble_q_kernel(const float* __restrict__ qc,
                                  const float* __restrict__ qr,
                                  const float* __restrict__ tab,
                                  float* __restrict__ q)
{
    int idx = blockIdx.x * blockDim.x + threadIdx.x;
    if (idx >= MM*HID) return;
    int d = idx & 127;
    int h = (idx >> 7) & 15;
    int t = idx >> 11;
    int s = t & (SS - 1);
    float val;
    if (d < CC) {
        val = qc[(long)t * (CC*NH) + h*CC + d];
    } else {
        int r = d - CC;
        int i = r & 15;
        float cs = tab[(s*16+i)*2+0];
        float sn = tab[(s*16+i)*2+1];
        const float* base = qr + (long)t * (RR*NH) + h*RR;
        float x = base[r];
        float xr = (r < 16) ? -base[r + 16] : base[r - 16];
        val = x * cs + xr * sn;
    }
    q[idx] = val;
}

__global__ void assemble_k_kernel(const float* __restrict__ kc,
                                  const float* __restrict__ kr,
                                  const float* __restrict__ tab,
                                  float* __restrict__ k)
{
    int idx = blockIdx.x * blockDim.x + threadIdx.x;
    if (idx >= MM*HID) return;
    int d = idx & 127;
    int h = (idx >> 7) & 15;
    int t = idx >> 11;
    int s = t & (SS - 1);
    float val;
    if (d < CC) {
        val = kc[(long)t * (CC*NH) + h*CC + d];
    } else {
        int r = d - CC;
        int i = r & 15;
        float cs = tab[(s*16+i)*2+0];
        float sn = tab[(s*16+i)*2+1];
        const float* base = kr + (long)t * RR;
        float x = base[r];
        float xr = (r < 16) ? -base[r + 16] : base[r - 16];
        val = x * cs + xr * sn;
    }
    k[idx] = val;
}

// ==================== Flash attention (causal, bf16 mma 3-pass) ====================
#define QST 136
#define VST 72

__global__ __launch_bounds__(128) void flash_mma_kernel(
    const float* __restrict__ Q, const float* __restrict__ Kt,
    const float* __restrict__ Vt, bf16* __restrict__ Oh, bf16* __restrict__ Ol)
{
    extern __shared__ bf16 smf[];
    bf16* Qh = smf;
    bf16* Ql = Qh + 64*QST;
    bf16* Kh = Ql + 64*QST;
    bf16* Kl = Kh + 64*QST;
    bf16* Vh = Kl + 64*QST;
    bf16* Vl = Vh + 128*VST;

    const int qb = blockIdx.x;
    const int h  = blockIdx.y;
    const int b  = blockIdx.z;
    const int tid = threadIdx.x;
    const int w = tid >> 5;
    const int lane = tid & 31;
    const int g = lane >> 2;
    const int tig = lane & 3;
    const int RS = NH * DH;
    const long base = ((long)b * SS * NH + h) * DH;
    const float scale = 0.08838834764831845f;

    {
        const float* src = Q + base + (long)(qb * 64) * RS;
#pragma unroll
        for (int it = 0; it < 16; it++) {
            int f = tid + it * 128;
            int row = f >> 5, c = (f & 31) << 2;
            float4 v = *(const float4*)(src + (long)row * RS + c);
            bf16 hx, lx, hy, ly, hz, lz, hw, lw;
            split_bf16(v.x, hx, lx); split_bf16(v.y, hy, ly);
            split_bf16(v.z, hz, lz); split_bf16(v.w, hw, lw);
            __nv_bfloat162* ph = (__nv_bfloat162*)&Qh[row*QST + c];
            __nv_bfloat162* pl = (__nv_bfloat162*)&Ql[row*QST + c];
            ph[0] = __nv_bfloat162(hx, hy); ph[1] = __nv_bfloat162(hz, hw);
            pl[0] = __nv_bfloat162(lx, ly); pl[1] = __nv_bfloat162(lz, lw);
        }
    }

    float m0 = -1e30f, m8 = -1e30f, l0 = 0.f, l8 = 0.f;
    float o[16][4];
#pragma unroll
    for (int nd = 0; nd < 16; nd++)
#pragma unroll
        for (int i = 0; i < 4; i++) o[nd][i] = 0.f;

    for (int kb = 0; kb <= qb; kb++) {
        const float* ksrc = Kt + base + (long)(kb * 64) * RS;
        const float* vsrc = Vt + base + (long)(kb * 64) * RS;
        __syncthreads();
#pragma unroll
        for (int it = 0; it < 16; it++) {
            int f = tid + it * 128;
            int row = f >> 5, c = (f & 31) << 2;
            float4 v = *(const float4*)(ksrc + (long)row * RS + c);
            bf16 hx, lx, hy, ly, hz, lz, hw, lw;
            split_bf16(v.x, hx, lx); split_bf16(v.y, hy, ly);
            split_bf16(v.z, hz, lz); split_bf16(v.w, hw, lw);
            __nv_bfloat162* ph = (__nv_bfloat162*)&Kh[row*QST + c];
            __nv_bfloat162* pl = (__nv_bfloat162*)&Kl[row*QST + c];
            ph[0] = __nv_bfloat162(hx, hy); ph[1] = __nv_bfloat162(hz, hw);
            pl[0] = __nv_bfloat162(lx, ly); pl[1] = __nv_bfloat162(lz, lw);
        }
#pragma unroll
        for (int it = 0; it < 16; it++) {
            int f = tid + it * 128;
            int row = f >> 5, c = (f & 31) << 2;
            float4 v = *(const float4*)(vsrc + (long)row * RS + c);
            bf16 hh, llo;
            split_bf16(v.x, hh, llo); Vh[(c+0)*VST + row] = hh; Vl[(c+0)*VST + row] = llo;
            split_bf16(v.y, hh, llo); Vh[(c+1)*VST + row] = hh; Vl[(c+1)*VST + row] = llo;
            split_bf16(v.z, hh, llo); Vh[(c+2)*VST + row] = hh; Vl[(c+2)*VST + row] = llo;
            split_bf16(v.w, hh, llo); Vh[(c+3)*VST + row] = hh; Vl[(c+3)*VST + row] = llo;
        }
        __syncthreads();

        float sc[8][4];
#pragma unroll
        for (int nt = 0; nt < 8; nt++)
#pragma unroll
            for (int i = 0; i < 4; i++) sc[nt][i] = 0.f;

#pragma unroll
        for (int kk = 0; kk < 128; kk += 16) {
            uint32_t ah[4], al[4];
            int a0 = (w*16 + g) * QST + kk + tig*2;
            int a1 = (w*16 + g + 8) * QST + kk + tig*2;
            ah[0] = *(const uint32_t*)&Qh[a0];
            ah[1] = *(const uint32_t*)&Qh[a1];
            ah[2] = *(const uint32_t*)&Qh[a0 + 8];
            ah[3] = *(const uint32_t*)&Qh[a1 + 8];
            al[0] = *(const uint32_t*)&Ql[a0];
            al[1] = *(const uint32_t*)&Ql[a1];
            al[2] = *(const uint32_t*)&Ql[a0 + 8];
            al[3] = *(const uint32_t*)&Ql[a1 + 8];
#pragma unroll
            for (int nt = 0; nt < 8; nt++) {
                uint32_t bh[2], bl[2];
                int b0 = (nt*8 + g) * QST + kk + tig*2;
                bh[0] = *(const uint32_t*)&Kh[b0];
                bh[1] = *(const uint32_t*)&Kh[b0 + 8];
                bl[0] = *(const uint32_t*)&Kl[b0];
                bl[1] = *(const uint32_t*)&Kl[b0 + 8];
                mma16816(sc[nt], ah, bh);
                mma16816(sc[nt], ah, bl);
                mma16816(sc[nt], al, bh);
            }
        }

#pragma unroll
        for (int nt = 0; nt < 8; nt++)
#pragma unroll
            for (int i = 0; i < 4; i++) sc[nt][i] *= scale;
        if (kb == qb) {
            int row0 = qb*64 + w*16 + g;
#pragma unroll
            for (int nt = 0; nt < 8; nt++) {
                int col = kb*64 + nt*8 + tig*2;
                if (col     > row0)     sc[nt][0] = -1e30f;
                if (col + 1 > row0)     sc[nt][1] = -1e30f;
                if (col     > row0 + 8) sc[nt][2] = -1e30f;
                if (col + 1 > row0 + 8) sc[nt][3] = -1e30f;
            }
        }

        float r0 = -1e30f, r8 = -1e30f;
#pragma unroll
        for (int nt = 0; nt < 8; nt++) {
            r0 = fmaxf(r0, fmaxf(sc[nt][0], sc[nt][1]));
            r8 = fmaxf(r8, fmaxf(sc[nt][2], sc[nt][3]));
        }
        r0 = fmaxf(r0, __shfl_xor_sync(0xffffffffu, r0, 1));
        r0 = fmaxf(r0, __shfl_xor_sync(0xffffffffu, r0, 2));
        r8 = fmaxf(r8, __shfl_xor_sync(0xffffffffu, r8, 1));
        r8 = fmaxf(r8, __shfl_xor_sync(0xffffffffu, r8, 2));
        float mn0 = fmaxf(m0, r0), mn8 = fmaxf(m8, r8);
        float alpha0 = __expf(m0 - mn0), alpha8 = __expf(m8 - mn8);
        float s0 = 0.f, s8 = 0.f;
#pragma unroll
        for (int nt = 0; nt < 8; nt++) {
            sc[nt][0] = __expf(sc[nt][0] - mn0);
            sc[nt][1] = __expf(sc[nt][1] - mn0);
            sc[nt][2] = __expf(sc[nt][2] - mn8);
            sc[nt][3] = __expf(sc[nt][3] - mn8);
            s0 += sc[nt][0] + sc[nt][1];
            s8 += sc[nt][2] + sc[nt][3];
        }
        s0 += __shfl_xor_sync(0xffffffffu, s0, 1);
        s0 += __shfl_xor_sync(0xffffffffu, s0, 2);
        s8 += __shfl_xor_sync(0xffffffffu, s8, 1);
        s8 += __shfl_xor_sync(0xffffffffu, s8, 2);
        l0 = l0 * alpha0 + s0; l8 = l8 * alpha8 + s8;
        m0 = mn0; m8 = mn8;
#pragma unroll
        for (int nd = 0; nd < 16; nd++) {
            o[nd][0] *= alpha0; o[nd][1] *= alpha0;
            o[nd][2] *= alpha8; o[nd][3] *= alpha8;
        }

#pragma unroll
        for (int t = 0; t < 4; t++) {
            uint32_t ph[4], pl[4];
            {
                float p00 = sc[2*t][0],   p01 = sc[2*t][1];
                float p02 = sc[2*t][2],   p03 = sc[2*t][3];
                float p10 = sc[2*t+1][0], p11 = sc[2*t+1][1];
                float p12 = sc[2*t+1][2], p13 = sc[2*t+1][3];
                ph[0] = pack_bf16(p00, p01);
                ph[1] = pack_bf16(p02, p03);
                ph[2] = pack_bf16(p10, p11);
                ph[3] = pack_bf16(p12, p13);
                __nv_bfloat162 hh;
                hh = *(__nv_bfloat162*)&ph[0];
                pl[0] = pack_bf16(p00 - bf16f(hh.x), p01 - bf16f(hh.y));
                hh = *(__nv_bfloat162*)&ph[1];
                pl[1] = pack_bf16(p02 - bf16f(hh.x), p03 - bf16f(hh.y));
                hh = *(__nv_bfloat162*)&ph[2];
                pl[2] = pack_bf16(p10 - bf16f(hh.x), p11 - bf16f(hh.y));
                hh = *(__nv_bfloat162*)&ph[3];
                pl[3] = pack_bf16(p12 - bf16f(hh.x), p13 - bf16f(hh.y));
            }
#pragma unroll
            for (int nd = 0; nd < 16; nd++) {
                uint32_t vh[2], vl[2];
                int b0 = (nd*8 + g) * VST + t*16 + tig*2;
                vh[0] = *(const uint32_t*)&Vh[b0];
                vh[1] = *(const uint32_t*)&Vh[b0 + 8];
                vl[0] = *(const uint32_t*)&Vl[b0];
                vl[1] = *(const uint32_t*)&Vl[b0 + 8];
                mma16816(o[nd], ph, vh);
                mma16816(o[nd], ph, vl);
                mma16816(o[nd], pl, vh);
            }
        }
    }

    // ---- write out: bf16 hi/lo planes (consumed by Wo GEMM) ----
    {
        float inv0 = 1.0f / l0, inv8 = 1.0f / l8;
        int row0 = qb*64 + w*16 + g;
        long i0 = base + (long)row0 * RS;
        long i8 = base + (long)(row0 + 8) * RS;
#pragma unroll
        for (int nd = 0; nd < 16; nd++) {
            int col = nd*8 + tig*2;
            float v0 = o[nd][0] * inv0, v1 = o[nd][1] * inv0;
            float v2 = o[nd][2] * inv8, v3 = o[nd][3] * inv8;
            bf16 h, l;
            split_bf16(v0, h, l); Oh[i0 + col]     = h; Ol[i0 + col]     = l;
            split_bf16(v1, h, l); Oh[i0 + col + 1] = h; Ol[i0 + col + 1] = l;
            split_bf16(v2, h, l); Oh[i8 + col]     = h; Ol[i8 + col]     = l;
            split_bf16(v3, h, l); Oh[i8 + col + 1] = h; Ol[i8 + col + 1] = l;
        }
    }
}

// ==================== launchers ====================
static inline void launch_split(const float* s, bf16* h, bf16* l, int n) {
    split_kernel<<<(n/4 + 255)/256, 256>>>(s, h, l, n);
}

static inline void launch_gemm(const bf16* Ah, const bf16* Al,
                               const bf16* Bh, const bf16* Bl,
                               const float* bias, float* C, bf16* Ch, bf16* Cl,
                               int M, int N, int K)
{
    if (N % 128 == 0) {
        constexpr int SMEM = 2 * (2*128 + 2*128) * 40 * 2;   // bytes
        cudaFuncSetAttribute(gemm_bf16_kernel<128,128,4,2>,
                             cudaFuncAttributeMaxDynamicSharedMemorySize, SMEM);
        dim3 grid(N / 128, M / 128);
        gemm_bf16_kernel<128,128,4,2><<<grid, 256, SMEM>>>(Ah, Al, Bh, Bl, bias, C, Ch, Cl, M, N, K);
    } else {
        constexpr int SMEM = 2 * (2*64 + 2*32) * 40 * 2;
        cudaFuncSetAttribute(gemm_bf16_kernel<64,32,4,2>,
                             cudaFuncAttributeMaxDynamicSharedMemorySize, SMEM);
        dim3 grid(N / 32, M / 64);
        gemm_bf16_kernel<64,32,4,2><<<grid, 256, SMEM>>>(Ah, Al, Bh, Bl, bias, C, Ch, Cl, M, N, K);
    }
}

#define SYM(p, s) cudaGetSymbolAddress((void**)&p, s)

extern "C" void kernel_launch(void* const* d_in, const int* in_sizes, int n_in,
                              void* d_out, int out_size)
{
    const float* x       = (const float*)d_in[0];
    const float* Wq_down = (const float*)d_in[1];
    const float* Wq_up   = (const float*)d_in[2];
    const float* Wq_rope = (const float*)d_in[3];
    const float* Wkv_down= (const float*)d_in[4];
    const float* Wk_up   = (const float*)d_in[5];
    const float* Wk_rope = (const float*)d_in[6];
    const float* Wv_up   = (const float*)d_in[7];
    const float* Wo      = (const float*)d_in[8];
    const float* bo      = (const float*)d_in[9];
    float* out = (float*)d_out;

    float *qc, *qr, *kc, *kr, *v, *q, *k, *tab;
    SYM(qc, g_qc); SYM(qr, g_qr); SYM(kc, g_kc); SYM(kr, g_kr);
    SYM(v, g_v);   SYM(q, g_q);   SYM(k, g_k);   SYM(tab, g_rope);
    bf16 *xh,*xl,*qlh,*qll,*kvh,*kvl,*cxh,*cxl;
    SYM(xh, g_xh); SYM(xl, g_xl); SYM(qlh, g_qlh); SYM(qll, g_qll);
    SYM(kvh, g_kvh); SYM(kvl, g_kvl); SYM(cxh, g_cxh); SYM(cxl, g_cxl);
    bf16 *wqdh,*wqdl,*wquh,*wqul,*wqrh,*wqrl,*wkdh,*wkdl,*wkuh,*wkul,*wkrh,*wkrl,*wvuh,*wvul,*woh,*wol;
    SYM(wqdh, g_wqdh); SYM(wqdl, g_wqdl); SYM(wquh, g_wquh); SYM(wqul, g_wqul);
    SYM(wqrh, g_wqrh); SYM(wqrl, g_wqrl); SYM(wkdh, g_wkdh); SYM(wkdl, g_wkdl);
    SYM(wkuh, g_wkuh); SYM(wkul, g_wkul); SYM(wkrh, g_wkrh); SYM(wkrl, g_wkrl);
    SYM(wvuh, g_wvuh); SYM(wvul, g_wvul); SYM(woh, g_woh);   SYM(wol, g_wol);

    rope_table_kernel<<<(SS*16 + 255)/256, 256>>>(tab);

    // fp32 -> bf16 hi/lo planes (inputs + weights)
    launch_split(x,        xh,   xl,   MM*HID);
    launch_split(Wq_down,  wqdh, wqdl, LAT*HID);
    launch_split(Wq_up,    wquh, wqul, CC*NH*LAT);
    launch_split(Wq_rope,  wqrh, wqrl, RR*NH*LAT);
    launch_split(Wkv_down, wkdh, wkdl, LAT*HID);
    launch_split(Wk_up,    wkuh, wkul, CC*NH*LAT);
    launch_split(Wk_rope,  wkrh, wkrl, RR*HID);
    launch_split(Wv_up,    wvuh, wvul, HID*LAT);
    launch_split(Wo,       woh,  wol,  HID*HID);

    // projections
    launch_gemm(xh, xl, wqdh, wqdl, nullptr, nullptr, qlh, qll, MM, LAT,   HID);
    launch_gemm(xh, xl, wkdh, wkdl, nullptr, nullptr, kvh, kvl, MM, LAT,   HID);
    launch_gemm(xh, xl, wkrh, wkrl, nullptr, kr, nullptr, nullptr, MM, RR, HID);
    launch_gemm(qlh, qll, wquh, wqul, nullptr, qc, nullptr, nullptr, MM, CC*NH, LAT);
    launch_gemm(qlh, qll, wqrh, wqrl, nullptr, qr, nullptr, nullptr, MM, RR*NH, LAT);
    launch_gemm(kvh, kvl, wkuh, wkul, nullptr, kc, nullptr, nullptr, MM, CC*NH, LAT);
    launch_gemm(kvh, kvl, wvuh, wvul, nullptr, v,  nullptr, nullptr, MM, HID,   LAT);

    // rope + head assembly
    {
        int total = MM * HID;
        int blocks = (total + 255) / 256;
        assemble_q_kernel<<<blocks, 256>>>(qc, qr, tab, q);
        assemble_k_kernel<<<blocks, 256>>>(kc, kr, tab, k);
    }

    // flash attention -> ctx bf16 planes
    {
        size_t smem = (size_t)(4*64*QST + 2*128*VST) * sizeof(bf16);
        cudaFuncSetAttribute(flash_mma_kernel,
                             cudaFuncAttributeMaxDynamicSharedMemorySize, (int)smem);
        dim3 grid(SS / 64, NH, BB);
        flash_mma_kernel<<<grid, 128, smem>>>(q, k, v, cxh, cxl);
    }

    // output projection + bias
    launch_gemm(cxh, cxl, woh, wol, bo, out, nullptr, nullptr, MM, HID, HID);
}

// round 9
// speedup vs baseline: 3.0452x; 1.4363x over previous
#include <cuda_runtime.h>
#include <cuda_bf16.h>
#include <math.h>
#include <stdint.h>

// Problem constants
#define HID 2048
#define NH  16
#define LAT 512
#define RR  32
#define DH  128
#define CC  96
#define BB  2
#define SS  2048
#define MM  (BB*SS)   // 4096

typedef __nv_bfloat16 bf16;

// ---------------- helpers ----------------
__device__ __forceinline__ void mma16816(float* c, const uint32_t* a, const uint32_t* b) {
    asm volatile(
        "mma.sync.aligned.m16n8k16.row.col.f32.bf16.bf16.f32 "
        "{%0,%1,%2,%3}, {%4,%5,%6,%7}, {%8,%9}, {%0,%1,%2,%3};"
        : "+f"(c[0]), "+f"(c[1]), "+f"(c[2]), "+f"(c[3])
        : "r"(a[0]), "r"(a[1]), "r"(a[2]), "r"(a[3]), "r"(b[0]), "r"(b[1]));
}
__device__ __forceinline__ void split_bf16(float x, bf16& h, bf16& l) {
    h = __float2bfloat16_rn(x);
    l = __float2bfloat16_rn(x - __bfloat162float(h));
}
__device__ __forceinline__ uint32_t pack_bf16(float lo, float hi) {
    __nv_bfloat162 t(__float2bfloat16_rn(lo), __float2bfloat16_rn(hi));
    return *(uint32_t*)&t;
}
__device__ __forceinline__ float bf16f(bf16 x) { return __bfloat162float(x); }
__device__ __forceinline__ uint32_t smem_u32(const void* p) {
    uint32_t a;
    asm("{ .reg .u64 t; cvta.to.shared.u64 t, %1; cvt.u32.u64 %0, t; }" : "=r"(a) : "l"(p));
    return a;
}
__device__ __forceinline__ void cp16(void* dst, const void* src) {
    asm volatile("cp.async.cg.shared.global [%0], [%1], 16;"
                 :: "r"(smem_u32(dst)), "l"(src));
}
#define CP_COMMIT() asm volatile("cp.async.commit_group;" ::: "memory")
#define CP_WAIT0()  asm volatile("cp.async.wait_group 0;" ::: "memory")
#define CP_WAIT1()  asm volatile("cp.async.wait_group 1;" ::: "memory")

// -------- scratch (device globals; no runtime allocation) --------
__device__ float g_qcqr[MM*2048];          // [qc | qr] fused, stride 2048
__device__ float g_kc [MM*(CC*NH)];
__device__ float g_kr [MM*RR];
__device__ float g_rope[SS*16*2];
// bf16 hi/lo planes
__device__ bf16 g_xh [MM*HID],  g_xl [MM*HID];
__device__ bf16 g_lath[MM*1024], g_latl[MM*1024];   // [qlat | kvlat] fused
__device__ bf16 g_qh [MM*HID],  g_ql [MM*HID];
__device__ bf16 g_kh [MM*HID],  g_kl [MM*HID];
__device__ bf16 g_vth[BB*NH*DH*SS], g_vtl[BB*NH*DH*SS];   // V transposed [b,h,d,s]
__device__ bf16 g_cxh[MM*HID],  g_cxl[MM*HID];
// weight planes (fused where consumers fuse)
__device__ bf16 g_wdh  [1024*HID], g_wdl  [1024*HID];     // [Wq_down ; Wkv_down]
__device__ bf16 g_wquph[2048*LAT], g_wqupl[2048*LAT];     // [Wq_up ; Wq_rope]
__device__ bf16 g_wkuh [CC*NH*LAT], g_wkul[CC*NH*LAT];
__device__ bf16 g_wkrh [RR*HID],   g_wkrl [RR*HID];
__device__ bf16 g_wvuh [HID*LAT],  g_wvul [HID*LAT];
__device__ bf16 g_woh  [HID*HID],  g_wol  [HID*HID];

// ==================== split: fp32 -> bf16 hi/lo planes ====================
__global__ void split_kernel(const float* __restrict__ src,
                             bf16* __restrict__ h, bf16* __restrict__ l, int n)
{
    int i = (blockIdx.x * blockDim.x + threadIdx.x) * 4;
    if (i >= n) return;
    float4 v = *(const float4*)(src + i);
    bf16 hx, lx, hy, ly, hz, lz, hw, lw;
    split_bf16(v.x, hx, lx); split_bf16(v.y, hy, ly);
    split_bf16(v.z, hz, lz); split_bf16(v.w, hw, lw);
    *(__nv_bfloat162*)(h + i)     = __nv_bfloat162(hx, hy);
    *(__nv_bfloat162*)(h + i + 2) = __nv_bfloat162(hz, hw);
    *(__nv_bfloat162*)(l + i)     = __nv_bfloat162(lx, ly);
    *(__nv_bfloat162*)(l + i + 2) = __nv_bfloat162(lz, lw);
}

// ==================== bf16-plane GEMM, cp.async 2-stage ====================
// C = (Ah+Al)[M,K](lda) @ (Bh+Bl)[N,K]^T, 3-pass.
// EPI 0: fp32 out (ldc) + optional bias.  EPI 1: bf16 planes out (ldc).
// EPI 2: bf16 planes out, V-transposed layout [b,h,d,s] (row=token, col=h*128+d).
template<int BM, int BN, int WARPS_M, int WARPS_N, int EPI>
__global__ __launch_bounds__(256) void gemm_bf16_kernel(
    const bf16* __restrict__ Ah, const bf16* __restrict__ Al,
    const bf16* __restrict__ Bh, const bf16* __restrict__ Bl,
    const float* __restrict__ bias, float* __restrict__ C,
    bf16* __restrict__ Oh, bf16* __restrict__ Ol,
    int M, int N, int K, int lda, int ldc)
{
    constexpr int BK = 32, ST = 40;
    constexpr int WTM = BM / WARPS_M;
    constexpr int WTN = BN / WARPS_N;
    constexpr int MT = WTM / 16;
    constexpr int NT = WTN / 8;
    constexpr int SSZ = (2*BM + 2*BN) * ST;

    extern __shared__ bf16 sm[];

    const int bm = blockIdx.y * BM;
    const int bn = blockIdx.x * BN;
    const int tid = threadIdx.x;
    const int wid = tid >> 5;
    const int lane = tid & 31;
    const int wm = wid / WARPS_N;
    const int wn = wid % WARPS_N;
    const int g = lane >> 2;
    const int tig = lane & 3;

    float acc[MT][NT][4];
#pragma unroll
    for (int mt = 0; mt < MT; mt++)
#pragma unroll
        for (int nt = 0; nt < NT; nt++)
#pragma unroll
            for (int i = 0; i < 4; i++) acc[mt][nt][i] = 0.f;

    const int nc = K / BK;

    auto load_stage = [&](int chunk, int s) {
        const long k0 = (long)chunk * BK;
        bf16* stg = sm + s * SSZ;
#pragma unroll
        for (int it = 0; it < (BM*4 + 255) / 256; it++) {
            int f = tid + it * 256;
            if (f < BM*4) {
                int row = f >> 2, cg = f & 3;
                long goff = (long)(bm + row) * lda + k0 + cg * 8;
                cp16(stg + row*ST + cg*8, Ah + goff);
                cp16(stg + BM*ST + row*ST + cg*8, Al + goff);
            }
        }
#pragma unroll
        for (int it = 0; it < (BN*4 + 255) / 256; it++) {
            int f = tid + it * 256;
            if (f < BN*4) {
                int row = f >> 2, cg = f & 3;
                long goff = (long)(bn + row) * K + k0 + cg * 8;
                cp16(stg + 2*BM*ST + row*ST + cg*8, Bh + goff);
                cp16(stg + 2*BM*ST + BN*ST + row*ST + cg*8, Bl + goff);
            }
        }
    };

    load_stage(0, 0);
    CP_COMMIT();

    for (int c = 0; c < nc; c++) {
        const int buf = c & 1;
        if (c + 1 < nc) {
            load_stage(c + 1, buf ^ 1);
            CP_COMMIT();
            CP_WAIT1();
        } else {
            CP_WAIT0();
        }
        __syncthreads();

        const bf16* sAh = sm + buf * SSZ;
        const bf16* sAl = sAh + BM*ST;
        const bf16* sBh = sAh + 2*BM*ST;
        const bf16* sBl = sBh + BN*ST;

#pragma unroll
        for (int kk = 0; kk < BK; kk += 16) {
            uint32_t afh[MT][4], afl[MT][4], bfh[NT][2], bfl[NT][2];
#pragma unroll
            for (int mt = 0; mt < MT; mt++) {
                int rb = wm * WTM + mt * 16;
                int a0 = (rb + g) * ST + kk + tig * 2;
                int a1 = (rb + g + 8) * ST + kk + tig * 2;
                afh[mt][0] = *(const uint32_t*)&sAh[a0];
                afh[mt][1] = *(const uint32_t*)&sAh[a1];
                afh[mt][2] = *(const uint32_t*)&sAh[a0 + 8];
                afh[mt][3] = *(const uint32_t*)&sAh[a1 + 8];
                afl[mt][0] = *(const uint32_t*)&sAl[a0];
                afl[mt][1] = *(const uint32_t*)&sAl[a1];
                afl[mt][2] = *(const uint32_t*)&sAl[a0 + 8];
                afl[mt][3] = *(const uint32_t*)&sAl[a1 + 8];
            }
#pragma unroll
            for (int nt = 0; nt < NT; nt++) {
                int nb = wn * WTN + nt * 8;
                int b0 = (nb + g) * ST + kk + tig * 2;
                bfh[nt][0] = *(const uint32_t*)&sBh[b0];
                bfh[nt][1] = *(const uint32_t*)&sBh[b0 + 8];
                bfl[nt][0] = *(const uint32_t*)&sBl[b0];
                bfl[nt][1] = *(const uint32_t*)&sBl[b0 + 8];
            }
#pragma unroll
            for (int mt = 0; mt < MT; mt++)
#pragma unroll
                for (int nt = 0; nt < NT; nt++) {
                    mma16816(acc[mt][nt], afh[mt], bfh[nt]);
                    mma16816(acc[mt][nt], afh[mt], bfl[nt]);
                    mma16816(acc[mt][nt], afl[mt], bfh[nt]);
                }
        }
        __syncthreads();
    }

    // ---- epilogue ----
#pragma unroll
    for (int mt = 0; mt < MT; mt++) {
        int row0 = bm + wm * WTM + mt * 16 + g;
#pragma unroll
        for (int nt = 0; nt < NT; nt++) {
            int col = bn + wn * WTN + nt * 8 + tig * 2;
            float v00 = acc[mt][nt][0], v01 = acc[mt][nt][1];
            float v10 = acc[mt][nt][2], v11 = acc[mt][nt][3];
            if (EPI == 0) {
                float b0 = bias ? bias[col] : 0.f;
                float b1 = bias ? bias[col + 1] : 0.f;
                *(float2*)&C[(long)row0 * ldc + col]       = make_float2(v00 + b0, v01 + b1);
                *(float2*)&C[(long)(row0 + 8) * ldc + col] = make_float2(v10 + b0, v11 + b1);
            } else if (EPI == 1) {
                long i0 = (long)row0 * ldc + col;
                long i1 = (long)(row0 + 8) * ldc + col;
                bf16 h, l;
                split_bf16(v00, h, l); Oh[i0]   = h; Ol[i0]   = l;
                split_bf16(v01, h, l); Oh[i0+1] = h; Ol[i0+1] = l;
                split_bf16(v10, h, l); Oh[i1]   = h; Ol[i1]   = l;
                split_bf16(v11, h, l); Oh[i1+1] = h; Ol[i1+1] = l;
            } else {
                // V-transposed: row=token -> (b, s); col -> (head, d); out [b,h,d,s]
                int s = row0 & (SS - 1);
                int bb = row0 >> 11;
                long i0 = ((long)(bb * NH + (col >> 7)) * DH + (col & 127)) * SS + s;
                bf16 h, l;
                split_bf16(v00, h, l); Oh[i0]        = h; Ol[i0]        = l;
                split_bf16(v01, h, l); Oh[i0+SS]     = h; Ol[i0+SS]     = l;
                split_bf16(v10, h, l); Oh[i0+8]      = h; Ol[i0+8]      = l;
                split_bf16(v11, h, l); Oh[i0+SS+8]   = h; Ol[i0+SS+8]   = l;
            }
        }
    }
}

// ==================== RoPE table ====================
__global__ void rope_table_kernel(float* __restrict__ tab)
{
    int idx = blockIdx.x * blockDim.x + threadIdx.x;
    if (idx >= SS * 16) return;
    int i = idx & 15;
    int s = idx >> 4;
    float inv = powf(10000.0f, -(float)i / 16.0f);
    float freq = (float)s * inv;
    float cs, sn;
    sincosf(freq, &sn, &cs);
    tab[idx*2+0] = cs;
    tab[idx*2+1] = sn;
}

// ==================== head assembly + RoPE -> bf16 planes ====================
__global__ void assemble_q_kernel(const float* __restrict__ qcqr,
                                  const float* __restrict__ tab,
                                  bf16* __restrict__ qh, bf16* __restrict__ ql)
{
    int idx = blockIdx.x * blockDim.x + threadIdx.x;
    if (idx >= MM*HID) return;
    int d = idx & 127;
    int h = (idx >> 7) & 15;
    int t = idx >> 11;
    int s = t & (SS - 1);
    float val;
    if (d < CC) {
        val = qcqr[(long)t * 2048 + h*CC + d];
    } else {
        int r = d - CC;
        int i = r & 15;
        float cs = tab[(s*16+i)*2+0];
        float sn = tab[(s*16+i)*2+1];
        const float* base = qcqr + (long)t * 2048 + 1536 + h*RR;
        float x = base[r];
        float xr = (r < 16) ? -base[r + 16] : base[r - 16];
        val = x * cs + xr * sn;
    }
    bf16 hh, ll;
    split_bf16(val, hh, ll);
    qh[idx] = hh; ql[idx] = ll;
}

__global__ void assemble_k_kernel(const float* __restrict__ kc,
                                  const float* __restrict__ kr,
                                  const float* __restrict__ tab,
                                  bf16* __restrict__ kh, bf16* __restrict__ kl)
{
    int idx = blockIdx.x * blockDim.x + threadIdx.x;
    if (idx >= MM*HID) return;
    int d = idx & 127;
    int h = (idx >> 7) & 15;
    int t = idx >> 11;
    int s = t & (SS - 1);
    float val;
    if (d < CC) {
        val = kc[(long)t * (CC*NH) + h*CC + d];
    } else {
        int r = d - CC;
        int i = r & 15;
        float cs = tab[(s*16+i)*2+0];
        float sn = tab[(s*16+i)*2+1];
        const float* base = kr + (long)t * RR;
        float x = base[r];
        float xr = (r < 16) ? -base[r + 16] : base[r - 16];
        val = x * cs + xr * sn;
    }
    bf16 hh, ll;
    split_bf16(val, hh, ll);
    kh[idx] = hh; kl[idx] = ll;
}

// ==================== Flash attention (causal, bf16 mma 3-pass) ====================
// Inputs are pre-split bf16 planes; V pre-transposed [b,h,d,s]. Pure cp.async staging.
#define QST 136
#define VST 72

__global__ __launch_bounds__(128) void flash_mma_kernel(
    const bf16* __restrict__ Qh_, const bf16* __restrict__ Ql_,
    const bf16* __restrict__ Kh_, const bf16* __restrict__ Kl_,
    const bf16* __restrict__ Vth_, const bf16* __restrict__ Vtl_,
    bf16* __restrict__ Oh, bf16* __restrict__ Ol)
{
    extern __shared__ bf16 smf[];
    bf16* sQh = smf;
    bf16* sQl = sQh + 64*QST;
    bf16* sKh = sQl + 64*QST;
    bf16* sKl = sKh + 64*QST;
    bf16* sVh = sKl + 64*QST;      // [d][t] 128 x VST
    bf16* sVl = sVh + 128*VST;

    const int qb = blockIdx.x;
    const int h  = blockIdx.y;
    const int b  = blockIdx.z;
    const int tid = threadIdx.x;
    const int w = tid >> 5;
    const int lane = tid & 31;
    const int g = lane >> 2;
    const int tig = lane & 3;
    const int RS = NH * DH;        // 2048
    const float scale = 0.08838834764831845f;

    // ---- Q tile via cp.async ----
    {
        const long qoff = ((long)b * SS + qb * 64) * RS + h * DH;
#pragma unroll
        for (int it = 0; it < 8; it++) {
            int f = tid + it * 128;
            int row = f >> 4, ch = (f & 15) * 8;
            cp16(sQh + row*QST + ch, Qh_ + qoff + (long)row * RS + ch);
            cp16(sQl + row*QST + ch, Ql_ + qoff + (long)row * RS + ch);
        }
        CP_COMMIT();
    }

    float m0 = -1e30f, m8 = -1e30f, l0 = 0.f, l8 = 0.f;
    float o[16][4];
#pragma unroll
    for (int nd = 0; nd < 16; nd++)
#pragma unroll
        for (int i = 0; i < 4; i++) o[nd][i] = 0.f;

    for (int kb = 0; kb <= qb; kb++) {
        __syncthreads();   // protect previous tile
        {
            const long koff = ((long)b * SS + kb * 64) * RS + h * DH;
#pragma unroll
            for (int it = 0; it < 8; it++) {
                int f = tid + it * 128;
                int row = f >> 4, ch = (f & 15) * 8;
                cp16(sKh + row*QST + ch, Kh_ + koff + (long)row * RS + ch);
                cp16(sKl + row*QST + ch, Kl_ + koff + (long)row * RS + ch);
            }
            const long voff = (long)(b * NH + h) * DH * SS + kb * 64;
#pragma unroll
            for (int it = 0; it < 8; it++) {
                int f = tid + it * 128;
                int row = f >> 3, ch = (f & 7) * 8;
                cp16(sVh + row*VST + ch, Vth_ + voff + (long)row * SS + ch);
                cp16(sVl + row*VST + ch, Vtl_ + voff + (long)row * SS + ch);
            }
            CP_COMMIT();
            CP_WAIT0();
        }
        __syncthreads();

        float sc[8][4];
#pragma unroll
        for (int nt = 0; nt < 8; nt++)
#pragma unroll
            for (int i = 0; i < 4; i++) sc[nt][i] = 0.f;

#pragma unroll
        for (int kk = 0; kk < 128; kk += 16) {
            uint32_t ah[4], al[4];
            int a0 = (w*16 + g) * QST + kk + tig*2;
            int a1 = (w*16 + g + 8) * QST + kk + tig*2;
            ah[0] = *(const uint32_t*)&sQh[a0];
            ah[1] = *(const uint32_t*)&sQh[a1];
            ah[2] = *(const uint32_t*)&sQh[a0 + 8];
            ah[3] = *(const uint32_t*)&sQh[a1 + 8];
            al[0] = *(const uint32_t*)&sQl[a0];
            al[1] = *(const uint32_t*)&sQl[a1];
            al[2] = *(const uint32_t*)&sQl[a0 + 8];
            al[3] = *(const uint32_t*)&sQl[a1 + 8];
#pragma unroll
            for (int nt = 0; nt < 8; nt++) {
                uint32_t bh[2], bl[2];
                int b0 = (nt*8 + g) * QST + kk + tig*2;
                bh[0] = *(const uint32_t*)&sKh[b0];
                bh[1] = *(const uint32_t*)&sKh[b0 + 8];
                bl[0] = *(const uint32_t*)&sKl[b0];
                bl[1] = *(const uint32_t*)&sKl[b0 + 8];
                mma16816(sc[nt], ah, bh);
                mma16816(sc[nt], ah, bl);
                mma16816(sc[nt], al, bh);
            }
        }

#pragma unroll
        for (int nt = 0; nt < 8; nt++)
#pragma unroll
            for (int i = 0; i < 4; i++) sc[nt][i] *= scale;
        if (kb == qb) {
            int row0 = qb*64 + w*16 + g;
#pragma unroll
            for (int nt = 0; nt < 8; nt++) {
                int col = kb*64 + nt*8 + tig*2;
                if (col     > row0)     sc[nt][0] = -1e30f;
                if (col + 1 > row0)     sc[nt][1] = -1e30f;
                if (col     > row0 + 8) sc[nt][2] = -1e30f;
                if (col + 1 > row0 + 8) sc[nt][3] = -1e30f;
            }
        }

        float r0 = -1e30f, r8 = -1e30f;
#pragma unroll
        for (int nt = 0; nt < 8; nt++) {
            r0 = fmaxf(r0, fmaxf(sc[nt][0], sc[nt][1]));
            r8 = fmaxf(r8, fmaxf(sc[nt][2], sc[nt][3]));
        }
        r0 = fmaxf(r0, __shfl_xor_sync(0xffffffffu, r0, 1));
        r0 = fmaxf(r0, __shfl_xor_sync(0xffffffffu, r0, 2));
        r8 = fmaxf(r8, __shfl_xor_sync(0xffffffffu, r8, 1));
        r8 = fmaxf(r8, __shfl_xor_sync(0xffffffffu, r8, 2));
        float mn0 = fmaxf(m0, r0), mn8 = fmaxf(m8, r8);
        float alpha0 = __expf(m0 - mn0), alpha8 = __expf(m8 - mn8);
        float s0 = 0.f, s8 = 0.f;
#pragma unroll
        for (int nt = 0; nt < 8; nt++) {
            sc[nt][0] = __expf(sc[nt][0] - mn0);
            sc[nt][1] = __expf(sc[nt][1] - mn0);
            sc[nt][2] = __expf(sc[nt][2] - mn8);
            sc[nt][3] = __expf(sc[nt][3] - mn8);
            s0 += sc[nt][0] + sc[nt][1];
            s8 += sc[nt][2] + sc[nt][3];
        }
        s0 += __shfl_xor_sync(0xffffffffu, s0, 1);
        s0 += __shfl_xor_sync(0xffffffffu, s0, 2);
        s8 += __shfl_xor_sync(0xffffffffu, s8, 1);
        s8 += __shfl_xor_sync(0xffffffffu, s8, 2);
        l0 = l0 * alpha0 + s0; l8 = l8 * alpha8 + s8;
        m0 = mn0; m8 = mn8;
#pragma unroll
        for (int nd = 0; nd < 16; nd++) {
            o[nd][0] *= alpha0; o[nd][1] *= alpha0;
            o[nd][2] *= alpha8; o[nd][3] *= alpha8;
        }

#pragma unroll
        for (int t = 0; t < 4; t++) {
            uint32_t ph[4], pl[4];
            {
                float p00 = sc[2*t][0],   p01 = sc[2*t][1];
                float p02 = sc[2*t][2],   p03 = sc[2*t][3];
                float p10 = sc[2*t+1][0], p11 = sc[2*t+1][1];
                float p12 = sc[2*t+1][2], p13 = sc[2*t+1][3];
                ph[0] = pack_bf16(p00, p01);
                ph[1] = pack_bf16(p02, p03);
                ph[2] = pack_bf16(p10, p11);
                ph[3] = pack_bf16(p12, p13);
                __nv_bfloat162 hh;
                hh = *(__nv_bfloat162*)&ph[0];
                pl[0] = pack_bf16(p00 - bf16f(hh.x), p01 - bf16f(hh.y));
                hh = *(__nv_bfloat162*)&ph[1];
                pl[1] = pack_bf16(p02 - bf16f(hh.x), p03 - bf16f(hh.y));
                hh = *(__nv_bfloat162*)&ph[2];
                pl[2] = pack_bf16(p10 - bf16f(hh.x), p11 - bf16f(hh.y));
                hh = *(__nv_bfloat162*)&ph[3];
                pl[3] = pack_bf16(p12 - bf16f(hh.x), p13 - bf16f(hh.y));
            }
#pragma unroll
            for (int nd = 0; nd < 16; nd++) {
                uint32_t vh[2], vl[2];
                int b0 = (nd*8 + g) * VST + t*16 + tig*2;
                vh[0] = *(const uint32_t*)&sVh[b0];
                vh[1] = *(const uint32_t*)&sVh[b0 + 8];
                vl[0] = *(const uint32_t*)&sVl[b0];
                vl[1] = *(const uint32_t*)&sVl[b0 + 8];
                mma16816(o[nd], ph, vh);
                mma16816(o[nd], ph, vl);
                mma16816(o[nd], pl, vh);
            }
        }
    }

    // ---- write ctx bf16 planes ----
    {
        float inv0 = 1.0f / l0, inv8 = 1.0f / l8;
        int row0 = qb*64 + w*16 + g;
        long i0 = ((long)b * SS + row0) * RS + h * DH;
        long i8 = i0 + 8L * RS;
#pragma unroll
        for (int nd = 0; nd < 16; nd++) {
            int col = nd*8 + tig*2;
            float v0 = o[nd][0] * inv0, v1 = o[nd][1] * inv0;
            float v2 = o[nd][2] * inv8, v3 = o[nd][3] * inv8;
            bf16 hh, ll;
            split_bf16(v0, hh, ll); Oh[i0 + col]     = hh; Ol[i0 + col]     = ll;
            split_bf16(v1, hh, ll); Oh[i0 + col + 1] = hh; Ol[i0 + col + 1] = ll;
            split_bf16(v2, hh, ll); Oh[i8 + col]     = hh; Ol[i8 + col]     = ll;
            split_bf16(v3, hh, ll); Oh[i8 + col + 1] = hh; Ol[i8 + col + 1] = ll;
        }
    }
}

// ==================== launchers ====================
static inline void launch_split(const float* s, bf16* h, bf16* l, int n) {
    split_kernel<<<(n/4 + 255)/256, 256>>>(s, h, l, n);
}

template<int EPI>
static void run_gemm(const bf16* Ah, const bf16* Al, const bf16* Bh, const bf16* Bl,
                     const float* bias, float* C, bf16* Oh, bf16* Ol,
                     int M, int N, int K, int lda, int ldc)
{
    if (N % 128 == 0) {
        constexpr int SMEM = 2 * (2*128 + 2*128) * 40 * 2;
        cudaFuncSetAttribute(gemm_bf16_kernel<128,128,4,2,EPI>,
                             cudaFuncAttributeMaxDynamicSharedMemorySize, SMEM);
        dim3 grid(N / 128, M / 128);
        gemm_bf16_kernel<128,128,4,2,EPI><<<grid, 256, SMEM>>>(
            Ah, Al, Bh, Bl, bias, C, Oh, Ol, M, N, K, lda, ldc);
    } else {
        constexpr int SMEM = 2 * (2*64 + 2*32) * 40 * 2;
        cudaFuncSetAttribute(gemm_bf16_kernel<64,32,4,2,EPI>,
                             cudaFuncAttributeMaxDynamicSharedMemorySize, SMEM);
        dim3 grid(N / 32, M / 64);
        gemm_bf16_kernel<64,32,4,2,EPI><<<grid, 256, SMEM>>>(
            Ah, Al, Bh, Bl, bias, C, Oh, Ol, M, N, K, lda, ldc);
    }
}

#define SYM(p, s) cudaGetSymbolAddress((void**)&p, s)

extern "C" void kernel_launch(void* const* d_in, const int* in_sizes, int n_in,
                              void* d_out, int out_size)
{
    const float* x       = (const float*)d_in[0];
    const float* Wq_down = (const float*)d_in[1];
    const float* Wq_up   = (const float*)d_in[2];
    const float* Wq_rope = (const float*)d_in[3];
    const float* Wkv_down= (const float*)d_in[4];
    const float* Wk_up   = (const float*)d_in[5];
    const float* Wk_rope = (const float*)d_in[6];
    const float* Wv_up   = (const float*)d_in[7];
    const float* Wo      = (const float*)d_in[8];
    const float* bo      = (const float*)d_in[9];
    float* out = (float*)d_out;

    float *qcqr, *kc, *kr, *tab;
    SYM(qcqr, g_qcqr); SYM(kc, g_kc); SYM(kr, g_kr); SYM(tab, g_rope);
    bf16 *xh,*xl,*lath,*latl,*qh,*ql,*kh,*kl,*vth,*vtl,*cxh,*cxl;
    SYM(xh, g_xh); SYM(xl, g_xl); SYM(lath, g_lath); SYM(latl, g_latl);
    SYM(qh, g_qh); SYM(ql, g_ql); SYM(kh, g_kh); SYM(kl, g_kl);
    SYM(vth, g_vth); SYM(vtl, g_vtl); SYM(cxh, g_cxh); SYM(cxl, g_cxl);
    bf16 *wdh,*wdl,*wquph,*wqupl,*wkuh,*wkul,*wkrh,*wkrl,*wvuh,*wvul,*woh,*wol;
    SYM(wdh, g_wdh); SYM(wdl, g_wdl); SYM(wquph, g_wquph); SYM(wqupl, g_wqupl);
    SYM(wkuh, g_wkuh); SYM(wkul, g_wkul); SYM(wkrh, g_wkrh); SYM(wkrl, g_wkrl);
    SYM(wvuh, g_wvuh); SYM(wvul, g_wvul); SYM(woh, g_woh); SYM(wol, g_wol);

    rope_table_kernel<<<(SS*16 + 255)/256, 256>>>(tab);

    // fp32 -> bf16 hi/lo planes (inputs + weights; fused weight layouts)
    launch_split(x,        xh, xl, MM*HID);
    launch_split(Wq_down,  wdh,              wdl,              LAT*HID);
    launch_split(Wkv_down, wdh + LAT*HID,    wdl + LAT*HID,    LAT*HID);
    launch_split(Wq_up,    wquph,            wqupl,            CC*NH*LAT);
    launch_split(Wq_rope,  wquph + CC*NH*LAT, wqupl + CC*NH*LAT, RR*NH*LAT);
    launch_split(Wk_up,    wkuh, wkul, CC*NH*LAT);
    launch_split(Wk_rope,  wkrh, wkrl, RR*HID);
    launch_split(Wv_up,    wvuh, wvul, HID*LAT);
    launch_split(Wo,       woh,  wol,  HID*HID);

    // fused down-projection: x -> [qlat | kvlat]  (bf16 planes)
    run_gemm<1>(xh, xl, wdh, wdl, nullptr, nullptr, lath, latl, MM, 1024, HID, HID, 1024);
    // k_rope: x -> kr (fp32)
    run_gemm<0>(xh, xl, wkrh, wkrl, nullptr, kr, nullptr, nullptr, MM, RR, HID, HID, RR);
    // fused q-up: qlat -> [qc | qr] (fp32)
    run_gemm<0>(lath, latl, wquph, wqupl, nullptr, qcqr, nullptr, nullptr, MM, 2048, LAT, 1024, 2048);
    // k-up: kvlat -> kc (fp32)
    run_gemm<0>(lath + 512, latl + 512, wkuh, wkul, nullptr, kc, nullptr, nullptr, MM, CC*NH, LAT, 1024, CC*NH);
    // v-up: kvlat -> V transposed bf16 planes
    run_gemm<2>(lath + 512, latl + 512, wvuh, wvul, nullptr, nullptr, vth, vtl, MM, HID, LAT, 1024, 0);

    // rope + head assembly -> bf16 planes
    {
        int blocks = (MM * HID + 255) / 256;
        assemble_q_kernel<<<blocks, 256>>>(qcqr, tab, qh, ql);
        assemble_k_kernel<<<blocks, 256>>>(kc, kr, tab, kh, kl);
    }

    // flash attention -> ctx bf16 planes
    {
        size_t smem = (size_t)(4*64*QST + 2*128*VST) * sizeof(bf16);
        cudaFuncSetAttribute(flash_mma_kernel,
                             cudaFuncAttributeMaxDynamicSharedMemorySize, (int)smem);
        dim3 grid(SS / 64, NH, BB);
        flash_mma_kernel<<<grid, 128, smem>>>(qh, ql, kh, kl, vth, vtl, cxh, cxl);
    }

    // output projection + bias
    run_gemm<0>(cxh, cxl, woh, wol, bo, out, nullptr, nullptr, MM, HID, HID, HID, HID);
}

// round 10
// speedup vs baseline: 3.4430x; 1.1306x over previous
#include <cuda_runtime.h>
#include <cuda_bf16.h>
#include <math.h>
#include <stdint.h>

// Problem constants
#define HID 2048
#define NH  16
#define LAT 512
#define RR  32
#define DH  128
#define CC  96
#define BB  2
#define SS  2048
#define MM  (BB*SS)   // 4096

typedef __nv_bfloat16 bf16;

// ---------------- helpers ----------------
__device__ __forceinline__ void mma16816(float* c, const uint32_t* a, const uint32_t* b) {
    asm volatile(
        "mma.sync.aligned.m16n8k16.row.col.f32.bf16.bf16.f32 "
        "{%0,%1,%2,%3}, {%4,%5,%6,%7}, {%8,%9}, {%0,%1,%2,%3};"
        : "+f"(c[0]), "+f"(c[1]), "+f"(c[2]), "+f"(c[3])
        : "r"(a[0]), "r"(a[1]), "r"(a[2]), "r"(a[3]), "r"(b[0]), "r"(b[1]));
}
__device__ __forceinline__ void ldsm_x4(uint32_t* r, uint32_t addr) {
    asm volatile("ldmatrix.sync.aligned.m8n8.x4.shared.b16 {%0,%1,%2,%3}, [%4];"
                 : "=r"(r[0]), "=r"(r[1]), "=r"(r[2]), "=r"(r[3]) : "r"(addr));
}
__device__ __forceinline__ void split_bf16(float x, bf16& h, bf16& l) {
    h = __float2bfloat16_rn(x);
    l = __float2bfloat16_rn(x - __bfloat162float(h));
}
__device__ __forceinline__ uint32_t pack_bf16(float lo, float hi) {
    __nv_bfloat162 t(__float2bfloat16_rn(lo), __float2bfloat16_rn(hi));
    return *(uint32_t*)&t;
}
__device__ __forceinline__ float bf16f(bf16 x) { return __bfloat162float(x); }
__device__ __forceinline__ uint32_t smem_u32(const void* p) {
    uint32_t a;
    asm("{ .reg .u64 t; cvta.to.shared.u64 t, %1; cvt.u32.u64 %0, t; }" : "=r"(a) : "l"(p));
    return a;
}
__device__ __forceinline__ void cp16(void* dst, const void* src) {
    asm volatile("cp.async.cg.shared.global [%0], [%1], 16;"
                 :: "r"(smem_u32(dst)), "l"(src));
}
#define CP_COMMIT() asm volatile("cp.async.commit_group;" ::: "memory")
#define CP_WAIT0()  asm volatile("cp.async.wait_group 0;" ::: "memory")
#define CP_WAIT1()  asm volatile("cp.async.wait_group 1;" ::: "memory")

// -------- scratch (device globals; no runtime allocation) --------
__device__ float g_qcqr[MM*2048];
__device__ float g_kc [MM*(CC*NH)];
__device__ float g_kr [MM*RR];
__device__ float g_rope[SS*16*2];
__device__ bf16 g_xh [MM*HID],  g_xl [MM*HID];
__device__ bf16 g_lath[MM*1024], g_latl[MM*1024];
__device__ bf16 g_qh [MM*HID],  g_ql [MM*HID];
__device__ bf16 g_kh [MM*HID],  g_kl [MM*HID];
__device__ bf16 g_vth[BB*NH*DH*SS], g_vtl[BB*NH*DH*SS];
__device__ bf16 g_cxh[MM*HID],  g_cxl[MM*HID];
__device__ bf16 g_wdh  [1024*HID], g_wdl  [1024*HID];
__device__ bf16 g_wquph[2048*LAT], g_wqupl[2048*LAT];
__device__ bf16 g_wkuh [CC*NH*LAT], g_wkul[CC*NH*LAT];
__device__ bf16 g_wkrh [RR*HID],   g_wkrl [RR*HID];
__device__ bf16 g_wvuh [HID*LAT],  g_wvul [HID*LAT];
__device__ bf16 g_woh  [HID*HID],  g_wol  [HID*HID];

// ==================== split ====================
__global__ void split_kernel(const float* __restrict__ src,
                             bf16* __restrict__ h, bf16* __restrict__ l, int n)
{
    int i = (blockIdx.x * blockDim.x + threadIdx.x) * 4;
    if (i >= n) return;
    float4 v = *(const float4*)(src + i);
    bf16 hx, lx, hy, ly, hz, lz, hw, lw;
    split_bf16(v.x, hx, lx); split_bf16(v.y, hy, ly);
    split_bf16(v.z, hz, lz); split_bf16(v.w, hw, lw);
    *(__nv_bfloat162*)(h + i)     = __nv_bfloat162(hx, hy);
    *(__nv_bfloat162*)(h + i + 2) = __nv_bfloat162(hz, hw);
    *(__nv_bfloat162*)(l + i)     = __nv_bfloat162(lx, ly);
    *(__nv_bfloat162*)(l + i + 2) = __nv_bfloat162(lz, lw);
}

// ==================== bf16-plane GEMM, cp.async + ldmatrix ====================
template<int BM, int BN, int WARPS_M, int WARPS_N, int EPI>
__global__ __launch_bounds__(256) void gemm_bf16_kernel(
    const bf16* __restrict__ Ah, const bf16* __restrict__ Al,
    const bf16* __restrict__ Bh, const bf16* __restrict__ Bl,
    const float* __restrict__ bias, float* __restrict__ C,
    bf16* __restrict__ Oh, bf16* __restrict__ Ol,
    int M, int N, int K, int lda, int ldc)
{
    constexpr int BK = 32, ST = 40;
    constexpr int WTM = BM / WARPS_M;
    constexpr int WTN = BN / WARPS_N;
    constexpr int MT = WTM / 16;
    constexpr int NT = WTN / 8;
    constexpr int SSZ = (2*BM + 2*BN) * ST;

    extern __shared__ bf16 sm[];

    const int bm = blockIdx.y * BM;
    const int bn = blockIdx.x * BN;
    const int tid = threadIdx.x;
    const int wid = tid >> 5;
    const int lane = tid & 31;
    const int wm = wid / WARPS_N;
    const int wn = wid % WARPS_N;
    const int g = lane >> 2;
    const int tig = lane & 3;
    // ldmatrix lane-address components
    const int lrowA = (lane & 7) + ((lane >> 3) & 1) * 8;   // row offset within 16
    const int lcolA = (lane >> 4) * 8;                      // col offset (0/8)
    const int mtx   = lane >> 3;
    const int lrowB = (mtx >> 1) * 8 + (lane & 7);
    const int lcolB = (mtx & 1) * 8;

    const uint32_t sm_u = smem_u32(sm);

    float acc[MT][NT][4];
#pragma unroll
    for (int mt = 0; mt < MT; mt++)
#pragma unroll
        for (int nt = 0; nt < NT; nt++)
#pragma unroll
            for (int i = 0; i < 4; i++) acc[mt][nt][i] = 0.f;

    const int nc = K / BK;

    auto load_stage = [&](int chunk, int s) {
        const long k0 = (long)chunk * BK;
        bf16* stg = sm + s * SSZ;
#pragma unroll
        for (int it = 0; it < (BM*4 + 255) / 256; it++) {
            int f = tid + it * 256;
            if (f < BM*4) {
                int row = f >> 2, cg = f & 3;
                long goff = (long)(bm + row) * lda + k0 + cg * 8;
                cp16(stg + row*ST + cg*8, Ah + goff);
                cp16(stg + BM*ST + row*ST + cg*8, Al + goff);
            }
        }
#pragma unroll
        for (int it = 0; it < (BN*4 + 255) / 256; it++) {
            int f = tid + it * 256;
            if (f < BN*4) {
                int row = f >> 2, cg = f & 3;
                long goff = (long)(bn + row) * K + k0 + cg * 8;
                cp16(stg + 2*BM*ST + row*ST + cg*8, Bh + goff);
                cp16(stg + 2*BM*ST + BN*ST + row*ST + cg*8, Bl + goff);
            }
        }
    };

    load_stage(0, 0);
    CP_COMMIT();

    for (int c = 0; c < nc; c++) {
        const int buf = c & 1;
        if (c + 1 < nc) {
            load_stage(c + 1, buf ^ 1);
            CP_COMMIT();
            CP_WAIT1();
        } else {
            CP_WAIT0();
        }
        __syncthreads();

        const uint32_t uAh = sm_u + (buf * SSZ) * 2;
        const uint32_t uAl = uAh + BM*ST*2;
        const uint32_t uBh = uAh + 2*BM*ST*2;
        const uint32_t uBl = uBh + BN*ST*2;

#pragma unroll
        for (int kk = 0; kk < BK; kk += 16) {
            uint32_t afh[MT][4], afl[MT][4], bfh[NT][2], bfl[NT][2];
#pragma unroll
            for (int mt = 0; mt < MT; mt++) {
                int off = ((wm*WTM + mt*16 + lrowA) * ST + kk + lcolA) * 2;
                ldsm_x4(afh[mt], uAh + off);
                ldsm_x4(afl[mt], uAl + off);
            }
#pragma unroll
            for (int np = 0; np < NT/2; np++) {
                int off = ((wn*WTN + np*16 + lrowB) * ST + kk + lcolB) * 2;
                uint32_t r[4];
                ldsm_x4(r, uBh + off);
                bfh[2*np][0]=r[0]; bfh[2*np][1]=r[1]; bfh[2*np+1][0]=r[2]; bfh[2*np+1][1]=r[3];
                ldsm_x4(r, uBl + off);
                bfl[2*np][0]=r[0]; bfl[2*np][1]=r[1]; bfl[2*np+1][0]=r[2]; bfl[2*np+1][1]=r[3];
            }
#pragma unroll
            for (int mt = 0; mt < MT; mt++)
#pragma unroll
                for (int nt = 0; nt < NT; nt++) {
                    mma16816(acc[mt][nt], afh[mt], bfh[nt]);
                    mma16816(acc[mt][nt], afh[mt], bfl[nt]);
                    mma16816(acc[mt][nt], afl[mt], bfh[nt]);
                }
        }
        __syncthreads();
    }

    // ---- epilogue ----
#pragma unroll
    for (int mt = 0; mt < MT; mt++) {
        int row0 = bm + wm * WTM + mt * 16 + g;
#pragma unroll
        for (int nt = 0; nt < NT; nt++) {
            int col = bn + wn * WTN + nt * 8 + tig * 2;
            float v00 = acc[mt][nt][0], v01 = acc[mt][nt][1];
            float v10 = acc[mt][nt][2], v11 = acc[mt][nt][3];
            if (EPI == 0) {
                float b0 = bias ? bias[col] : 0.f;
                float b1 = bias ? bias[col + 1] : 0.f;
                *(float2*)&C[(long)row0 * ldc + col]       = make_float2(v00 + b0, v01 + b1);
                *(float2*)&C[(long)(row0 + 8) * ldc + col] = make_float2(v10 + b0, v11 + b1);
            } else if (EPI == 1) {
                long i0 = (long)row0 * ldc + col;
                long i1 = (long)(row0 + 8) * ldc + col;
                bf16 h, l;
                split_bf16(v00, h, l); Oh[i0]   = h; Ol[i0]   = l;
                split_bf16(v01, h, l); Oh[i0+1] = h; Ol[i0+1] = l;
                split_bf16(v10, h, l); Oh[i1]   = h; Ol[i1]   = l;
                split_bf16(v11, h, l); Oh[i1+1] = h; Ol[i1+1] = l;
            } else {
                int s = row0 & (SS - 1);
                int bb = row0 >> 11;
                long i0 = ((long)(bb * NH + (col >> 7)) * DH + (col & 127)) * SS + s;
                bf16 h, l;
                split_bf16(v00, h, l); Oh[i0]      = h; Ol[i0]      = l;
                split_bf16(v01, h, l); Oh[i0+SS]   = h; Ol[i0+SS]   = l;
                split_bf16(v10, h, l); Oh[i0+8]    = h; Ol[i0+8]    = l;
                split_bf16(v11, h, l); Oh[i0+SS+8] = h; Ol[i0+SS+8] = l;
            }
        }
    }
}

// ==================== RoPE table ====================
__global__ void rope_table_kernel(float* __restrict__ tab)
{
    int idx = blockIdx.x * blockDim.x + threadIdx.x;
    if (idx >= SS * 16) return;
    int i = idx & 15;
    int s = idx >> 4;
    float inv = powf(10000.0f, -(float)i / 16.0f);
    float freq = (float)s * inv;
    float cs, sn;
    sincosf(freq, &sn, &cs);
    tab[idx*2+0] = cs;
    tab[idx*2+1] = sn;
}

// ==================== head assembly + RoPE -> bf16 planes ====================
__global__ void assemble_q_kernel(const float* __restrict__ qcqr,
                                  const float* __restrict__ tab,
                                  bf16* __restrict__ qh, bf16* __restrict__ ql)
{
    int idx = blockIdx.x * blockDim.x + threadIdx.x;
    if (idx >= MM*HID) return;
    int d = idx & 127;
    int h = (idx >> 7) & 15;
    int t = idx >> 11;
    int s = t & (SS - 1);
    float val;
    if (d < CC) {
        val = qcqr[(long)t * 2048 + h*CC + d];
    } else {
        int r = d - CC;
        int i = r & 15;
        float cs = tab[(s*16+i)*2+0];
        float sn = tab[(s*16+i)*2+1];
        const float* base = qcqr + (long)t * 2048 + 1536 + h*RR;
        float x = base[r];
        float xr = (r < 16) ? -base[r + 16] : base[r - 16];
        val = x * cs + xr * sn;
    }
    bf16 hh, ll;
    split_bf16(val, hh, ll);
    qh[idx] = hh; ql[idx] = ll;
}

__global__ void assemble_k_kernel(const float* __restrict__ kc,
                                  const float* __restrict__ kr,
                                  const float* __restrict__ tab,
                                  bf16* __restrict__ kh, bf16* __restrict__ kl)
{
    int idx = blockIdx.x * blockDim.x + threadIdx.x;
    if (idx >= MM*HID) return;
    int d = idx & 127;
    int h = (idx >> 7) & 15;
    int t = idx >> 11;
    int s = t & (SS - 1);
    float val;
    if (d < CC) {
        val = kc[(long)t * (CC*NH) + h*CC + d];
    } else {
        int r = d - CC;
        int i = r & 15;
        float cs = tab[(s*16+i)*2+0];
        float sn = tab[(s*16+i)*2+1];
        const float* base = kr + (long)t * RR;
        float x = base[r];
        float xr = (r < 16) ? -base[r + 16] : base[r - 16];
        val = x * cs + xr * sn;
    }
    bf16 hh, ll;
    split_bf16(val, hh, ll);
    kh[idx] = hh; kl[idx] = ll;
}

// ==================== Flash attention (bf16 mma 3-pass, ldmatrix) ====================
#define QST 136
#define VST 72

__global__ __launch_bounds__(128) void flash_mma_kernel(
    const bf16* __restrict__ Qh_, const bf16* __restrict__ Ql_,
    const bf16* __restrict__ Kh_, const bf16* __restrict__ Kl_,
    const bf16* __restrict__ Vth_, const bf16* __restrict__ Vtl_,
    bf16* __restrict__ Oh, bf16* __restrict__ Ol)
{
    extern __shared__ bf16 smf[];
    bf16* sQh = smf;
    bf16* sQl = sQh + 64*QST;
    bf16* sKh = sQl + 64*QST;
    bf16* sKl = sKh + 64*QST;
    bf16* sVh = sKl + 64*QST;
    bf16* sVl = sVh + 128*VST;

    const int qb = blockIdx.x;
    const int h  = blockIdx.y;
    const int b  = blockIdx.z;
    const int tid = threadIdx.x;
    const int w = tid >> 5;
    const int lane = tid & 31;
    const int g = lane >> 2;
    const int tig = lane & 3;
    const int RS = NH * DH;
    const float scale = 0.08838834764831845f;
    const int lrowA = (lane & 7) + ((lane >> 3) & 1) * 8;
    const int lcolA = (lane >> 4) * 8;
    const int mtx   = lane >> 3;
    const int lrowB = (mtx >> 1) * 8 + (lane & 7);
    const int lcolB = (mtx & 1) * 8;

    const uint32_t uQh = smem_u32(sQh), uQl = smem_u32(sQl);
    const uint32_t uKh = smem_u32(sKh), uKl = smem_u32(sKl);
    const uint32_t uVh = smem_u32(sVh), uVl = smem_u32(sVl);

    {
        const long qoff = ((long)b * SS + qb * 64) * RS + h * DH;
#pragma unroll
        for (int it = 0; it < 8; it++) {
            int f = tid + it * 128;
            int row = f >> 4, ch = (f & 15) * 8;
            cp16(sQh + row*QST + ch, Qh_ + qoff + (long)row * RS + ch);
            cp16(sQl + row*QST + ch, Ql_ + qoff + (long)row * RS + ch);
        }
        CP_COMMIT();
    }

    float m0 = -1e30f, m8 = -1e30f, l0 = 0.f, l8 = 0.f;
    float o[16][4];
#pragma unroll
    for (int nd = 0; nd < 16; nd++)
#pragma unroll
        for (int i = 0; i < 4; i++) o[nd][i] = 0.f;

    for (int kb = 0; kb <= qb; kb++) {
        __syncthreads();
        {
            const long koff = ((long)b * SS + kb * 64) * RS + h * DH;
#pragma unroll
            for (int it = 0; it < 8; it++) {
                int f = tid + it * 128;
                int row = f >> 4, ch = (f & 15) * 8;
                cp16(sKh + row*QST + ch, Kh_ + koff + (long)row * RS + ch);
                cp16(sKl + row*QST + ch, Kl_ + koff + (long)row * RS + ch);
            }
            const long voff = (long)(b * NH + h) * DH * SS + kb * 64;
#pragma unroll
            for (int it = 0; it < 8; it++) {
                int f = tid + it * 128;
                int row = f >> 3, ch = (f & 7) * 8;
                cp16(sVh + row*VST + ch, Vth_ + voff + (long)row * SS + ch);
                cp16(sVl + row*VST + ch, Vtl_ + voff + (long)row * SS + ch);
            }
            CP_COMMIT();
            CP_WAIT0();
        }
        __syncthreads();

        float sc[8][4];
#pragma unroll
        for (int nt = 0; nt < 8; nt++)
#pragma unroll
            for (int i = 0; i < 4; i++) sc[nt][i] = 0.f;

#pragma unroll
        for (int kk = 0; kk < 128; kk += 16) {
            uint32_t ah[4], al[4];
            {
                int off = ((w*16 + lrowA) * QST + kk + lcolA) * 2;
                ldsm_x4(ah, uQh + off);
                ldsm_x4(al, uQl + off);
            }
            uint32_t bh[8][2], bl[8][2];
#pragma unroll
            for (int np = 0; np < 4; np++) {
                int off = ((np*16 + lrowB) * QST + kk + lcolB) * 2;
                uint32_t r[4];
                ldsm_x4(r, uKh + off);
                bh[2*np][0]=r[0]; bh[2*np][1]=r[1]; bh[2*np+1][0]=r[2]; bh[2*np+1][1]=r[3];
                ldsm_x4(r, uKl + off);
                bl[2*np][0]=r[0]; bl[2*np][1]=r[1]; bl[2*np+1][0]=r[2]; bl[2*np+1][1]=r[3];
            }
#pragma unroll
            for (int nt = 0; nt < 8; nt++) {
                mma16816(sc[nt], ah, bh[nt]);
                mma16816(sc[nt], ah, bl[nt]);
                mma16816(sc[nt], al, bh[nt]);
            }
        }

#pragma unroll
        for (int nt = 0; nt < 8; nt++)
#pragma unroll
            for (int i = 0; i < 4; i++) sc[nt][i] *= scale;
        if (kb == qb) {
            int row0 = qb*64 + w*16 + g;
#pragma unroll
            for (int nt = 0; nt < 8; nt++) {
                int col = kb*64 + nt*8 + tig*2;
                if (col     > row0)     sc[nt][0] = -1e30f;
                if (col + 1 > row0)     sc[nt][1] = -1e30f;
                if (col     > row0 + 8) sc[nt][2] = -1e30f;
                if (col + 1 > row0 + 8) sc[nt][3] = -1e30f;
            }
        }

        float r0 = -1e30f, r8 = -1e30f;
#pragma unroll
        for (int nt = 0; nt < 8; nt++) {
            r0 = fmaxf(r0, fmaxf(sc[nt][0], sc[nt][1]));
            r8 = fmaxf(r8, fmaxf(sc[nt][2], sc[nt][3]));
        }
        r0 = fmaxf(r0, __shfl_xor_sync(0xffffffffu, r0, 1));
        r0 = fmaxf(r0, __shfl_xor_sync(0xffffffffu, r0, 2));
        r8 = fmaxf(r8, __shfl_xor_sync(0xffffffffu, r8, 1));
        r8 = fmaxf(r8, __shfl_xor_sync(0xffffffffu, r8, 2));
        float mn0 = fmaxf(m0, r0), mn8 = fmaxf(m8, r8);
        float alpha0 = __expf(m0 - mn0), alpha8 = __expf(m8 - mn8);
        float s0 = 0.f, s8 = 0.f;
#pragma unroll
        for (int nt = 0; nt < 8; nt++) {
            sc[nt][0] = __expf(sc[nt][0] - mn0);
            sc[nt][1] = __expf(sc[nt][1] - mn0);
            sc[nt][2] = __expf(sc[nt][2] - mn8);
            sc[nt][3] = __expf(sc[nt][3] - mn8);
            s0 += sc[nt][0] + sc[nt][1];
            s8 += sc[nt][2] + sc[nt][3];
        }
        s0 += __shfl_xor_sync(0xffffffffu, s0, 1);
        s0 += __shfl_xor_sync(0xffffffffu, s0, 2);
        s8 += __shfl_xor_sync(0xffffffffu, s8, 1);
        s8 += __shfl_xor_sync(0xffffffffu, s8, 2);
        l0 = l0 * alpha0 + s0; l8 = l8 * alpha8 + s8;
        m0 = mn0; m8 = mn8;
#pragma unroll
        for (int nd = 0; nd < 16; nd++) {
            o[nd][0] *= alpha0; o[nd][1] *= alpha0;
            o[nd][2] *= alpha8; o[nd][3] *= alpha8;
        }

#pragma unroll
        for (int t = 0; t < 4; t++) {
            uint32_t ph[4], pl[4];
            {
                float p00 = sc[2*t][0],   p01 = sc[2*t][1];
                float p02 = sc[2*t][2],   p03 = sc[2*t][3];
                float p10 = sc[2*t+1][0], p11 = sc[2*t+1][1];
                float p12 = sc[2*t+1][2], p13 = sc[2*t+1][3];
                ph[0] = pack_bf16(p00, p01);
                ph[1] = pack_bf16(p02, p03);
                ph[2] = pack_bf16(p10, p11);
                ph[3] = pack_bf16(p12, p13);
                __nv_bfloat162 hh;
                hh = *(__nv_bfloat162*)&ph[0];
                pl[0] = pack_bf16(p00 - bf16f(hh.x), p01 - bf16f(hh.y));
                hh = *(__nv_bfloat162*)&ph[1];
                pl[1] = pack_bf16(p02 - bf16f(hh.x), p03 - bf16f(hh.y));
                hh = *(__nv_bfloat162*)&ph[2];
                pl[2] = pack_bf16(p10 - bf16f(hh.x), p11 - bf16f(hh.y));
                hh = *(__nv_bfloat162*)&ph[3];
                pl[3] = pack_bf16(p12 - bf16f(hh.x), p13 - bf16f(hh.y));
            }
#pragma unroll
            for (int np = 0; np < 8; np++) {
                int off = ((np*16 + lrowB) * VST + t*16 + lcolB) * 2;
                uint32_t vh[4], vl[4];
                ldsm_x4(vh, uVh + off);
                ldsm_x4(vl, uVl + off);
                mma16816(o[2*np],   ph, vh);
                mma16816(o[2*np],   ph, vl);
                mma16816(o[2*np],   pl, vh);
                mma16816(o[2*np+1], ph, vh + 2);
                mma16816(o[2*np+1], ph, vl + 2);
                mma16816(o[2*np+1], pl, vh + 2);
            }
        }
    }

    // ---- write ctx bf16 planes ----
    {
        float inv0 = 1.0f / l0, inv8 = 1.0f / l8;
        int row0 = qb*64 + w*16 + g;
        long i0 = ((long)b * SS + row0) * RS + h * DH;
        long i8 = i0 + 8L * RS;
#pragma unroll
        for (int nd = 0; nd < 16; nd++) {
            int col = nd*8 + tig*2;
            float v0 = o[nd][0] * inv0, v1 = o[nd][1] * inv0;
            float v2 = o[nd][2] * inv8, v3 = o[nd][3] * inv8;
            bf16 hh, ll;
            split_bf16(v0, hh, ll); Oh[i0 + col]     = hh; Ol[i0 + col]     = ll;
            split_bf16(v1, hh, ll); Oh[i0 + col + 1] = hh; Ol[i0 + col + 1] = ll;
            split_bf16(v2, hh, ll); Oh[i8 + col]     = hh; Ol[i8 + col]     = ll;
            split_bf16(v3, hh, ll); Oh[i8 + col + 1] = hh; Ol[i8 + col + 1] = ll;
        }
    }
}

// ==================== launchers ====================
static inline void launch_split(const float* s, bf16* h, bf16* l, int n) {
    split_kernel<<<(n/4 + 255)/256, 256>>>(s, h, l, n);
}

template<int EPI>
static void run_gemm(const bf16* Ah, const bf16* Al, const bf16* Bh, const bf16* Bl,
                     const float* bias, float* C, bf16* Oh, bf16* Ol,
                     int M, int N, int K, int lda, int ldc)
{
    if (N % 128 == 0) {
        constexpr int SMEM = 2 * (2*128 + 2*128) * 40 * 2;
        cudaFuncSetAttribute(gemm_bf16_kernel<128,128,4,2,EPI>,
                             cudaFuncAttributeMaxDynamicSharedMemorySize, SMEM);
        dim3 grid(N / 128, M / 128);
        gemm_bf16_kernel<128,128,4,2,EPI><<<grid, 256, SMEM>>>(
            Ah, Al, Bh, Bl, bias, C, Oh, Ol, M, N, K, lda, ldc);
    } else {
        constexpr int SMEM = 2 * (2*64 + 2*32) * 40 * 2;
        cudaFuncSetAttribute(gemm_bf16_kernel<64,32,4,2,EPI>,
                             cudaFuncAttributeMaxDynamicSharedMemorySize, SMEM);
        dim3 grid(N / 32, M / 64);
        gemm_bf16_kernel<64,32,4,2,EPI><<<grid, 256, SMEM>>>(
            Ah, Al, Bh, Bl, bias, C, Oh, Ol, M, N, K, lda, ldc);
    }
}

#define SYM(p, s) cudaGetSymbolAddress((void**)&p, s)

extern "C" void kernel_launch(void* const* d_in, const int* in_sizes, int n_in,
                              void* d_out, int out_size)
{
    const float* x       = (const float*)d_in[0];
    const float* Wq_down = (const float*)d_in[1];
    const float* Wq_up   = (const float*)d_in[2];
    const float* Wq_rope = (const float*)d_in[3];
    const float* Wkv_down= (const float*)d_in[4];
    const float* Wk_up   = (const float*)d_in[5];
    const float* Wk_rope = (const float*)d_in[6];
    const float* Wv_up   = (const float*)d_in[7];
    const float* Wo      = (const float*)d_in[8];
    const float* bo      = (const float*)d_in[9];
    float* out = (float*)d_out;

    float *qcqr, *kc, *kr, *tab;
    SYM(qcqr, g_qcqr); SYM(kc, g_kc); SYM(kr, g_kr); SYM(tab, g_rope);
    bf16 *xh,*xl,*lath,*latl,*qh,*ql,*kh,*kl,*vth,*vtl,*cxh,*cxl;
    SYM(xh, g_xh); SYM(xl, g_xl); SYM(lath, g_lath); SYM(latl, g_latl);
    SYM(qh, g_qh); SYM(ql, g_ql); SYM(kh, g_kh); SYM(kl, g_kl);
    SYM(vth, g_vth); SYM(vtl, g_vtl); SYM(cxh, g_cxh); SYM(cxl, g_cxl);
    bf16 *wdh,*wdl,*wquph,*wqupl,*wkuh,*wkul,*wkrh,*wkrl,*wvuh,*wvul,*woh,*wol;
    SYM(wdh, g_wdh); SYM(wdl, g_wdl); SYM(wquph, g_wquph); SYM(wqupl, g_wqupl);
    SYM(wkuh, g_wkuh); SYM(wkul, g_wkul); SYM(wkrh, g_wkrh); SYM(wkrl, g_wkrl);
    SYM(wvuh, g_wvuh); SYM(wvul, g_wvul); SYM(woh, g_woh); SYM(wol, g_wol);

    // ordering note: launch #6 (1-indexed) is the big fused down-GEMM so the
    // ncu capture (-s 5 -c 1) profiles it.
    launch_split(x,        xh, xl, MM*HID);                                   // 1
    launch_split(Wq_down,  wdh,           wdl,           LAT*HID);            // 2
    launch_split(Wkv_down, wdh + LAT*HID, wdl + LAT*HID, LAT*HID);            // 3
    rope_table_kernel<<<(SS*16 + 255)/256, 256>>>(tab);                       // 4
    launch_split(Wk_rope,  wkrh, wkrl, RR*HID);                               // 5
    // fused down-projection: x -> [qlat | kvlat]                              // 6
    run_gemm<1>(xh, xl, wdh, wdl, nullptr, nullptr, lath, latl, MM, 1024, HID, HID, 1024);

    launch_split(Wq_up,    wquph,             wqupl,             CC*NH*LAT);
    launch_split(Wq_rope,  wquph + CC*NH*LAT, wqupl + CC*NH*LAT, RR*NH*LAT);
    launch_split(Wk_up,    wkuh, wkul, CC*NH*LAT);
    launch_split(Wv_up,    wvuh, wvul, HID*LAT);
    launch_split(Wo,       woh,  wol,  HID*HID);

    run_gemm<0>(xh, xl, wkrh, wkrl, nullptr, kr, nullptr, nullptr, MM, RR, HID, HID, RR);
    run_gemm<0>(lath, latl, wquph, wqupl, nullptr, qcqr, nullptr, nullptr, MM, 2048, LAT, 1024, 2048);
    run_gemm<0>(lath + 512, latl + 512, wkuh, wkul, nullptr, kc, nullptr, nullptr, MM, CC*NH, LAT, 1024, CC*NH);
    run_gemm<2>(lath + 512, latl + 512, wvuh, wvul, nullptr, nullptr, vth, vtl, MM, HID, LAT, 1024, 0);

    {
        int blocks = (MM * HID + 255) / 256;
        assemble_q_kernel<<<blocks, 256>>>(qcqr, tab, qh, ql);
        assemble_k_kernel<<<blocks, 256>>>(kc, kr, tab, kh, kl);
    }

    {
        size_t smem = (size_t)(4*64*QST + 2*128*VST) * sizeof(bf16);
        cudaFuncSetAttribute(flash_mma_kernel,
                             cudaFuncAttributeMaxDynamicSharedMemorySize, (int)smem);
        dim3 grid(SS / 64, NH, BB);
        flash_mma_kernel<<<grid, 128, smem>>>(qh, ql, kh, kl, vth, vtl, cxh, cxl);
    }

    run_gemm<0>(cxh, cxl, woh, wol, bo, out, nullptr, nullptr, MM, HID, HID, HID, HID);
}